// round 3
// baseline (speedup 1.0000x reference)
#include <cuda_runtime.h>
#include <cuda_bf16.h>
#include <math.h>
#include <stdint.h>

#define Bsz 2
#define Cch 64
#define Hh  256
#define Ww  1216
#define HWs (Hh*Ww)          // 311296
#define NS  20000
#define Kn  9
#define Dd  131
#define Dhh 65
#define ICP 16               // halves per (row,col) cell in A smem

// conv tile geometry
#define TR 8                 // tile rows
#define TC 32                // tile cols
#define HR (TR+2)            // halo rows 10
#define HC (TC+2)            // halo cols 34
#define A_ELEMS (HR*HC*ICP)  // 5440 per part
// dynamic smem offsets (bytes)
#define OFF_AL (A_ELEMS*2)           // 10880
#define OFF_BF (2*A_ELEMS*2)         // 21760
#define SMEM_BYTES (OFF_BF + 9216*4) // 58624

// ---------------- scratch (device globals: allocation-free) ----------------
__device__ float g_d0[(size_t)Bsz*Cch*HWs];
__device__ float g_r0[(size_t)Bsz*Cch*HWs];
__device__ float g_dfeat[(size_t)Bsz*Cch*NS];
__device__ float g_rfeat[(size_t)Bsz*Cch*NS];
// packed weight fragments: 6 sets x [part2][chunk4][tap9][nf8][lane32][pair2]
#define WSET_U32 36864
__device__ uint32_t g_wfrag[6*WSET_U32];

// ---------------- helpers ---------------------------------------------------
__device__ __forceinline__ uint32_t pack_bf2(float a, float b) {
    __nv_bfloat162 t;
    t.x = __float2bfloat16(a);
    t.y = __float2bfloat16(b);
    return *reinterpret_cast<uint32_t*>(&t);
}

__device__ __forceinline__ void mma_bf16(float c[4], const uint32_t a[4],
                                         uint32_t b0, uint32_t b1) {
    asm volatile(
        "mma.sync.aligned.m16n8k16.row.col.f32.bf16.bf16.f32 "
        "{%0,%1,%2,%3}, {%4,%5,%6,%7}, {%8,%9}, {%0,%1,%2,%3};"
        : "+f"(c[0]), "+f"(c[1]), "+f"(c[2]), "+f"(c[3])
        : "r"(a[0]), "r"(a[1]), "r"(a[2]), "r"(a[3]), "r"(b0), "r"(b1));
}

__device__ __forceinline__ void ldsm4(uint32_t a[4], uint32_t addr) {
    asm volatile("ldmatrix.sync.aligned.m8n8.x4.shared.b16 {%0,%1,%2,%3}, [%4];"
                 : "=r"(a[0]), "=r"(a[1]), "=r"(a[2]), "=r"(a[3]) : "r"(addr));
}

// ---------------- weight prepack: fp32 OIHW -> bf16 hi/lo mma fragments ----
__global__ void prepack_w(const float* __restrict__ w0, const float* __restrict__ w1,
                          const float* __restrict__ w2, const float* __restrict__ w3,
                          const float* __restrict__ w4, const float* __restrict__ w5)
{
    const float* w;
    switch (blockIdx.y) {
        case 0: w = w0; break; case 1: w = w1; break; case 2: w = w2; break;
        case 3: w = w3; break; case 4: w = w4; break; default: w = w5; break;
    }
    uint32_t* dst = g_wfrag + blockIdx.y * WSET_U32;

    int cb = blockIdx.x;
    int chunk = cb / 72;
    int rem = cb % 72;
    int tap = rem / 8;
    int nf = rem % 8;
    int lane = threadIdx.x;

    int oc = nf*8 + (lane >> 2);
    int k0 = (lane & 3) * 2;
    int ic = chunk*16 + k0;

    float v00 = w[oc*576 + ic*9 + tap];
    float v01 = w[oc*576 + (ic+1)*9 + tap];
    float v10 = w[oc*576 + (ic+8)*9 + tap];
    float v11 = w[oc*576 + (ic+9)*9 + tap];

    float h00 = __bfloat162float(__float2bfloat16(v00));
    float h01 = __bfloat162float(__float2bfloat16(v01));
    float h10 = __bfloat162float(__float2bfloat16(v10));
    float h11 = __bfloat162float(__float2bfloat16(v11));

    size_t base0 = ((((size_t)0*4 + chunk)*9 + tap)*8 + nf)*64 + lane*2;
    dst[base0 + 0] = pack_bf2(h00, h01);
    dst[base0 + 1] = pack_bf2(h10, h11);
    size_t base1 = ((((size_t)1*4 + chunk)*9 + tap)*8 + nf)*64 + lane*2;
    dst[base1 + 0] = pack_bf2(v00 - h00, v01 - h01);
    dst[base1 + 1] = pack_bf2(v10 - h10, v11 - h11);
}

// ---------------- conv 3x3 SAME via mma (split bf16), up to 2 sources ------
// Block 256 thr (8 warps). Tile: 8 rows x 32 cols x 64 oc.
// Warp = 1 image row, M=32 (two m16 frags share B registers).
__global__ __launch_bounds__(256, 2) void conv3x3_mma(
    const float* __restrict__ x0, const uint32_t* __restrict__ wf0,
    const float* __restrict__ x1, const uint32_t* __restrict__ wf1,
    const float* __restrict__ b0, const float* __restrict__ b1,
    float* __restrict__ y)
{
    extern __shared__ __align__(16) unsigned char sraw[];
    __nv_bfloat16* s_ah = (__nv_bfloat16*)sraw;
    __nv_bfloat16* s_al = (__nv_bfloat16*)(sraw + OFF_AL);
    uint32_t*      s_bf = (uint32_t*)(sraw + OFF_BF);
    float*         s_out = (float*)sraw;    // alias, 128*66 floats per pass

    const int tid  = threadIdx.x;
    const int lane = tid & 31;
    const int wid  = tid >> 5;
    const int w0c  = blockIdx.x * TC;
    const int h0   = blockIdx.y * TR;
    const int b    = blockIdx.z;

    float c[2][8][4];
#pragma unroll
    for (int mf = 0; mf < 2; mf++)
#pragma unroll
        for (int nf = 0; nf < 8; nf++)
#pragma unroll
            for (int j = 0; j < 4; j++) c[mf][nf][j] = 0.f;

    const int mm   = lane & 15;
    const int kofs = (lane >> 4) << 3;

    uint32_t a_hi_base = (uint32_t)__cvta_generic_to_shared(s_ah);
    uint32_t a_lo_base = (uint32_t)__cvta_generic_to_shared(s_al);

#pragma unroll 1
    for (int src = 0; src < 2; src++) {
        const float* xs = src ? x1 : x0;
        const uint32_t* wf = src ? wf1 : wf0;
        if (xs == nullptr) break;
        const float* xb = xs + (size_t)b * Cch * HWs;

#pragma unroll 1
        for (int cc = 0; cc < 4; cc++) {
            __syncthreads();
            // ---- load + split A halo tile: 16 ic x 10 rows x 34 cols ----
            for (int i = tid; i < A_ELEMS; i += 256) {
                int ic   = i / (HR*HC);
                int rem  = i % (HR*HC);
                int rowh = rem / HC;
                int col  = rem % HC;
                int h  = h0 - 1 + rowh;
                int wc = w0c - 1 + col;
                float v = 0.f;
                if ((unsigned)h < (unsigned)Hh && (unsigned)wc < (unsigned)Ww)
                    v = xb[(size_t)(cc*16 + ic) * HWs + (size_t)h * Ww + wc];
                __nv_bfloat16 hi = __float2bfloat16(v);
                float lo = v - __bfloat162float(hi);
                int si = (rowh*HC + col)*ICP + ic;
                s_ah[si] = hi;
                s_al[si] = __float2bfloat16(lo);
            }
            // ---- load B fragments for this chunk (hi and lo parts) ----
            for (int i = tid; i < 9216; i += 256) {
                int p = i / 4608;
                int j = i - p*4608;
                s_bf[i] = wf[(size_t)(p*4 + cc)*4608 + j];
            }
            __syncthreads();

            // ---- compute: 9 taps, 2 m-frags sharing B regs ----
#pragma unroll
            for (int tap = 0; tap < 9; tap++) {
                const int dy = tap / 3, dx = tap % 3;
                uint32_t ai0 = (uint32_t)((((wid + dy)*HC) + (mm + dx))*ICP + kofs) * 2u;
                uint32_t ai1 = ai0 + (uint32_t)(16*ICP*2);
                uint32_t ah0[4], al0[4], ah1[4], al1[4];
                ldsm4(ah0, a_hi_base + ai0);
                ldsm4(al0, a_lo_base + ai0);
                ldsm4(ah1, a_hi_base + ai1);
                ldsm4(al1, a_lo_base + ai1);
#pragma unroll
                for (int nf = 0; nf < 8; nf++) {
                    uint2 bh = *(const uint2*)&s_bf[(tap*8 + nf)*64 + lane*2];
                    uint2 bl = *(const uint2*)&s_bf[((9 + tap)*8 + nf)*64 + lane*2];
                    mma_bf16(c[0][nf], ah0, bh.x, bh.y);
                    mma_bf16(c[1][nf], ah1, bh.x, bh.y);
                    mma_bf16(c[0][nf], ah0, bl.x, bl.y);
                    mma_bf16(c[1][nf], ah1, bl.x, bl.y);
                    mma_bf16(c[0][nf], al0, bh.x, bh.y);
                    mma_bf16(c[1][nf], al1, bh.x, bh.y);
                }
            }
        }
    }

    // ---- epilogue: two passes of 128 pixels (16-col halves) through smem ----
#pragma unroll 1
    for (int mf = 0; mf < 2; mf++) {
        __syncthreads();
        {
            int pix0 = wid*16 + (lane >> 2);
            int oc0  = (lane & 3) * 2;
#pragma unroll
            for (int nf = 0; nf < 8; nf++) {
                int oc = nf*8 + oc0;
                s_out[pix0*66 + oc]         = c[mf][nf][0];
                s_out[pix0*66 + oc + 1]     = c[mf][nf][1];
                s_out[(pix0+8)*66 + oc]     = c[mf][nf][2];
                s_out[(pix0+8)*66 + oc + 1] = c[mf][nf][3];
            }
        }
        __syncthreads();
        for (int i = tid; i < 8192; i += 256) {
            int oc = i >> 7;
            int pix = i & 127;
            float bias = b0[oc] + (b1 ? b1[oc] : 0.f);
            float v = s_out[pix*66 + oc] + bias;
            v = fmaxf(v, 0.f);
            y[((size_t)(b*Cch + oc))*HWs + (size_t)(h0 + (pix >> 4))*Ww
              + (w0c + mf*16 + (pix & 15))] = v;
        }
    }
}

// ---------------- point stage: gather + 2 MLPs + softmax + weighted sum ----
__global__ __launch_bounds__(128) void point_kernel(
    const int* __restrict__ pc, const int* __restrict__ nbrs,
    const float* __restrict__ disp,
    const float* __restrict__ d_w1, const float* __restrict__ d_b1,
    const float* __restrict__ d_w2, const float* __restrict__ d_b2,
    const float* __restrict__ r_w1, const float* __restrict__ r_b1,
    const float* __restrict__ r_w2, const float* __restrict__ r_b2,
    const float* __restrict__ d_bias, const float* __restrict__ r_bias)
{
    const int n  = blockIdx.x;
    const int b  = blockIdx.y;
    const int tid = threadIdx.x;

    __shared__ float s_ds[64], s_rs[64];
    __shared__ float s_dnn[64][9];
    __shared__ float s_feat[9][132];
    __shared__ float s_h[2][9][66];
    __shared__ float s_logit[2][9];
    __shared__ float s_attn[2][9];
    __shared__ int   s_nb[9];
    __shared__ int   s_pidx;

    if (tid == 0) s_pidx = pc[(size_t)b*NS + n];
    if (tid < Kn) s_nb[tid] = nbrs[((size_t)b*NS + n)*Kn + tid];
    __syncthreads();

    const float* d0b = g_d0 + (size_t)b * Cch * HWs;
    const float* r0b = g_r0 + (size_t)b * Cch * HWs;
    const int pidx = s_pidx;

    if (tid < 64) {
        s_ds[tid] = d0b[(size_t)tid * HWs + pidx];
        s_rs[tid] = r0b[(size_t)tid * HWs + pidx];
    }
    for (int i = tid; i < 64*Kn; i += 128) {
        int ch = i / Kn, k = i % Kn;
        s_dnn[ch][k] = d0b[(size_t)ch * HWs + s_nb[k]];
    }
    if (tid < 3*Kn) {
        int c3 = tid / Kn, k = tid % Kn;
        s_feat[k][128 + c3] = disp[(((size_t)b*3 + c3)*NS + n)*Kn + k];
    }
    __syncthreads();

    for (int i = tid; i < 64*Kn; i += 128) {
        int ch = i / Kn, k = i % Kn;
        float dn = s_dnn[ch][k];
        s_feat[k][ch]      = dn - s_ds[ch];
        s_feat[k][64 + ch] = dn - s_rs[ch];
    }
    __syncthreads();

    for (int t = tid; t < 2*Kn*Dhh; t += 128) {
        int m = t / (Kn*Dhh);
        int local = t % (Kn*Dhh);
        int k = local / Dhh;
        int j = local % Dhh;
        const float* W1 = m ? r_w1 : d_w1;
        float a = (m ? r_b1 : d_b1)[j];
#pragma unroll 1
        for (int d = 0; d < Dd; d++)
            a = fmaf(s_feat[k][d], __ldg(&W1[d*Dhh + j]), a);
        a = (a > 0.f) ? a : 0.2f * a;
        s_h[m][k][j] = a;
    }
    __syncthreads();

    if (tid < 2*Kn) {
        int m = tid / Kn, k = tid % Kn;
        const float* W2 = m ? r_w2 : d_w2;
        float a = (m ? r_b2 : d_b2)[0];
#pragma unroll 1
        for (int j = 0; j < Dhh; j++)
            a = fmaf(s_h[m][k][j], __ldg(&W2[j]), a);
        s_logit[m][k] = a;
    }
    __syncthreads();

    if (tid < 2) {
        int m = tid;
        float mx = s_logit[m][0];
#pragma unroll
        for (int k = 1; k < Kn; k++) mx = fmaxf(mx, s_logit[m][k]);
        float sum = 0.f;
        float e[Kn];
#pragma unroll
        for (int k = 0; k < Kn; k++) { e[k] = expf(s_logit[m][k] - mx); sum += e[k]; }
        float inv = 1.f / sum;
#pragma unroll
        for (int k = 0; k < Kn; k++) s_attn[m][k] = e[k] * inv;
    }
    __syncthreads();

    if (tid < 64) {
        int ch = tid;
        float a = d_bias[ch];
#pragma unroll
        for (int k = 0; k < Kn; k++) a = fmaf(s_attn[0][k], s_dnn[ch][k], a);
        g_dfeat[((size_t)b*Cch + ch)*NS + n] = a;
    } else if (tid < 128) {
        int ch = tid - 64;
        float a = r_bias[ch];
#pragma unroll
        for (int k = 0; k < Kn; k++) a = fmaf(s_attn[1][k], s_dnn[ch][k], a);
        g_rfeat[((size_t)b*Cch + ch)*NS + n] = a;
    }
}

// ---------------- scatter update (pc indices unique -> race-free) ----------
__global__ __launch_bounds__(128) void scatter_kernel(const int* __restrict__ pc)
{
    const int n = blockIdx.x;
    const int b = blockIdx.y;
    const int tid = threadIdx.x;
    const int idx = pc[(size_t)b*NS + n];

    if (tid < 64) {
        int ch = tid;
        float v = g_dfeat[((size_t)b*Cch + ch)*NS + n];
        size_t o = ((size_t)b*Cch + ch)*HWs + idx;
        g_d0[o] = (ch == 0) ? v : (g_d0[o] + v);
    } else {
        int ch = tid - 64;
        float v = g_rfeat[((size_t)b*Cch + ch)*NS + n];
        size_t o = ((size_t)b*Cch + ch)*HWs + idx;
        g_r0[o] = (ch == 0) ? v : (g_r0[o] + v);
    }
}

// ---------------------------------------------------------------------------
extern "C" void kernel_launch(void* const* d_in, const int* in_sizes, int n_in,
                              void* d_out, int out_size)
{
    const float* rgb    = (const float*)d_in[0];
    const float* sdepth = (const float*)d_in[1];
    const int*   pc     = (const int*)  d_in[2];
    const int*   nbrs   = (const int*)  d_in[3];
    const float* disp   = (const float*)d_in[4];
    const float* d_c0w  = (const float*)d_in[5];
    const float* d_c0b  = (const float*)d_in[6];
    const float* d_c1w  = (const float*)d_in[7];
    const float* d_c1b  = (const float*)d_in[8];
    const float* d_c2w  = (const float*)d_in[9];
    const float* d_c2b  = (const float*)d_in[10];
    const float* r_c0w  = (const float*)d_in[11];
    const float* r_c0b  = (const float*)d_in[12];
    const float* r_c1w  = (const float*)d_in[13];
    const float* r_c1b  = (const float*)d_in[14];
    const float* r_c2w  = (const float*)d_in[15];
    const float* r_c2b  = (const float*)d_in[16];
    const float* d_w1   = (const float*)d_in[17];
    const float* d_b1   = (const float*)d_in[18];
    const float* d_w2   = (const float*)d_in[19];
    const float* d_b2   = (const float*)d_in[20];
    const float* r_w1   = (const float*)d_in[21];
    const float* r_b1   = (const float*)d_in[22];
    const float* r_w2   = (const float*)d_in[23];
    const float* r_b2   = (const float*)d_in[24];
    const float* d_bias = (const float*)d_in[25];
    const float* r_bias = (const float*)d_in[26];
    float* out = (float*)d_out;

    float *p_gd0, *p_gr0;
    uint32_t* p_wf;
    cudaGetSymbolAddress((void**)&p_gd0, g_d0);
    cudaGetSymbolAddress((void**)&p_gr0, g_r0);
    cudaGetSymbolAddress((void**)&p_wf, g_wfrag);

    cudaFuncSetAttribute(conv3x3_mma,
                         cudaFuncAttributeMaxDynamicSharedMemorySize, SMEM_BYTES);

    // weight prepack: sets 0:d0 1:r0 2:d2 3:d1 4:r2 5:r1
    prepack_w<<<dim3(288, 6), 32>>>(d_c0w, r_c0w, d_c2w, d_c1w, r_c2w, r_c1w);

    dim3 cgrid(Ww/TC, Hh/TR, Bsz);

    // Stage A
    conv3x3_mma<<<cgrid, 256, SMEM_BYTES>>>(sdepth, p_wf + 0*WSET_U32, nullptr, nullptr,
                                            d_c0b, nullptr, p_gd0);
    conv3x3_mma<<<cgrid, 256, SMEM_BYTES>>>(rgb,    p_wf + 1*WSET_U32, nullptr, nullptr,
                                            r_c0b, nullptr, p_gr0);

    // Stage B
    point_kernel<<<dim3(NS, Bsz), 128>>>(pc, nbrs, disp,
                                         d_w1, d_b1, d_w2, d_b2,
                                         r_w1, r_b1, r_w2, r_b2,
                                         d_bias, r_bias);
    scatter_kernel<<<dim3(NS, Bsz), 128>>>(pc);

    // Stage C (fused dual-source convs)
    conv3x3_mma<<<cgrid, 256, SMEM_BYTES>>>(p_gd0, p_wf + 2*WSET_U32, sdepth, p_wf + 3*WSET_U32,
                                            d_c2b, d_c1b, out);
    conv3x3_mma<<<cgrid, 256, SMEM_BYTES>>>(p_gr0, p_wf + 4*WSET_U32, rgb, p_wf + 5*WSET_U32,
                                            r_c2b, r_c1b, out + (size_t)Bsz*Cch*HWs);
}

// round 4
// speedup vs baseline: 1.0317x; 1.0317x over previous
#include <cuda_runtime.h>
#include <cuda_bf16.h>
#include <math.h>
#include <stdint.h>

#define Bsz 2
#define Cch 64
#define Hh  256
#define Ww  1216
#define HWs (Hh*Ww)          // 311296
#define NS  20000
#define Kn  9
#define Dd  131
#define Dhh 65
#define ICP 16               // halves per (row,col) cell in A smem

// conv tile geometry
#define TR 8                 // tile rows
#define TC 32                // tile cols
#define HR (TR+2)            // halo rows 10
#define HC (TC+2)            // halo cols 34
#define A_ELEMS (HR*HC*ICP)  // 5440 per part
// dynamic smem offsets (bytes)
#define OFF_AL (A_ELEMS*2)           // 10880
#define OFF_BF (2*A_ELEMS*2)         // 21760
#define SMEM_BYTES (OFF_BF + 9216*4) // 58624

// ---------------- scratch (device globals: allocation-free) ----------------
__device__ float g_d0[(size_t)Bsz*Cch*HWs];
__device__ float g_r0[(size_t)Bsz*Cch*HWs];
__device__ float g_dfeat[(size_t)Bsz*Cch*NS];
__device__ float g_rfeat[(size_t)Bsz*Cch*NS];
// packed weight fragments: 6 sets x [chunk4][tap9][nf8][lane32][4u32: bh0,bh1,bl0,bl1]
#define WSET_U32 36864
__device__ uint32_t g_wfrag[6*WSET_U32];

// ---------------- helpers ---------------------------------------------------
__device__ __forceinline__ uint32_t pack_bf2(float a, float b) {
    __nv_bfloat162 t;
    t.x = __float2bfloat16(a);
    t.y = __float2bfloat16(b);
    return *reinterpret_cast<uint32_t*>(&t);
}

__device__ __forceinline__ void mma_bf16(float c[4], const uint32_t a[4],
                                         uint32_t b0, uint32_t b1) {
    asm volatile(
        "mma.sync.aligned.m16n8k16.row.col.f32.bf16.bf16.f32 "
        "{%0,%1,%2,%3}, {%4,%5,%6,%7}, {%8,%9}, {%0,%1,%2,%3};"
        : "+f"(c[0]), "+f"(c[1]), "+f"(c[2]), "+f"(c[3])
        : "r"(a[0]), "r"(a[1]), "r"(a[2]), "r"(a[3]), "r"(b0), "r"(b1));
}

__device__ __forceinline__ void ldsm4(uint32_t a[4], uint32_t addr) {
    asm volatile("ldmatrix.sync.aligned.m8n8.x4.shared.b16 {%0,%1,%2,%3}, [%4];"
                 : "=r"(a[0]), "=r"(a[1]), "=r"(a[2]), "=r"(a[3]) : "r"(addr));
}

// ---------------- weight prepack: fp32 OIHW -> bf16 hi/lo mma fragments ----
// grid (288, 6), block 32.  288 = chunk4 * tap9 * nf8
__global__ void prepack_w(const float* __restrict__ w0, const float* __restrict__ w1,
                          const float* __restrict__ w2, const float* __restrict__ w3,
                          const float* __restrict__ w4, const float* __restrict__ w5)
{
    const float* w;
    switch (blockIdx.y) {
        case 0: w = w0; break; case 1: w = w1; break; case 2: w = w2; break;
        case 3: w = w3; break; case 4: w = w4; break; default: w = w5; break;
    }
    uint32_t* dst = g_wfrag + blockIdx.y * WSET_U32;

    int cb = blockIdx.x;
    int chunk = cb / 72;
    int rem = cb % 72;
    int tap = rem / 8;
    int nf = rem % 8;
    int lane = threadIdx.x;

    int oc = nf*8 + (lane >> 2);
    int k0 = (lane & 3) * 2;
    int ic = chunk*16 + k0;

    float v00 = w[oc*576 + ic*9 + tap];
    float v01 = w[oc*576 + (ic+1)*9 + tap];
    float v10 = w[oc*576 + (ic+8)*9 + tap];
    float v11 = w[oc*576 + (ic+9)*9 + tap];

    float h00 = __bfloat162float(__float2bfloat16(v00));
    float h01 = __bfloat162float(__float2bfloat16(v01));
    float h10 = __bfloat162float(__float2bfloat16(v10));
    float h11 = __bfloat162float(__float2bfloat16(v11));

    size_t base = ((((size_t)chunk*9 + tap)*8 + nf)*32 + lane)*4;
    dst[base + 0] = pack_bf2(h00, h01);
    dst[base + 1] = pack_bf2(h10, h11);
    dst[base + 2] = pack_bf2(v00 - h00, v01 - h01);
    dst[base + 3] = pack_bf2(v10 - h10, v11 - h11);
}

// ---------------- conv 3x3 SAME via mma (split bf16), up to 2 sources ------
// Block 256 thr (8 warps). Tile: 8 rows x 32 cols x 64 oc.
// Warp = 1 image row, M=32 (two m16 frags share B registers).
__global__ __launch_bounds__(256, 2) void conv3x3_mma(
    const float* __restrict__ x0, const uint32_t* __restrict__ wf0,
    const float* __restrict__ x1, const uint32_t* __restrict__ wf1,
    const float* __restrict__ b0, const float* __restrict__ b1,
    float* __restrict__ y)
{
    extern __shared__ __align__(16) unsigned char sraw[];
    __nv_bfloat16* s_ah = (__nv_bfloat16*)sraw;
    __nv_bfloat16* s_al = (__nv_bfloat16*)(sraw + OFF_AL);
    uint32_t*      s_bf = (uint32_t*)(sraw + OFF_BF);
    float*         s_out = (float*)sraw;    // alias, 128*66 floats per pass

    const int tid  = threadIdx.x;
    const int lane = tid & 31;
    const int wid  = tid >> 5;
    const int w0c  = blockIdx.x * TC;
    const int h0   = blockIdx.y * TR;
    const int b    = blockIdx.z;

    float c[2][8][4];
#pragma unroll
    for (int mf = 0; mf < 2; mf++)
#pragma unroll
        for (int nf = 0; nf < 8; nf++)
#pragma unroll
            for (int j = 0; j < 4; j++) c[mf][nf][j] = 0.f;

    const int mm   = lane & 15;
    const int kofs = (lane >> 4) << 3;

    uint32_t a_hi_base = (uint32_t)__cvta_generic_to_shared(s_ah);
    uint32_t a_lo_base = (uint32_t)__cvta_generic_to_shared(s_al);

#pragma unroll 1
    for (int src = 0; src < 2; src++) {
        const float* xs = src ? x1 : x0;
        const uint32_t* wf = src ? wf1 : wf0;
        if (xs == nullptr) break;
        const float* xb = xs + (size_t)b * Cch * HWs;

#pragma unroll 1
        for (int cc = 0; cc < 4; cc++) {
            __syncthreads();
            // ---- load + split A halo tile: 16 ic x 10 rows x 34 cols ----
            for (int i = tid; i < A_ELEMS; i += 256) {
                int ic   = i / (HR*HC);
                int rem  = i % (HR*HC);
                int rowh = rem / HC;
                int col  = rem % HC;
                int h  = h0 - 1 + rowh;
                int wc = w0c - 1 + col;
                float v = 0.f;
                if ((unsigned)h < (unsigned)Hh && (unsigned)wc < (unsigned)Ww)
                    v = xb[(size_t)(cc*16 + ic) * HWs + (size_t)h * Ww + wc];
                __nv_bfloat16 hi = __float2bfloat16(v);
                float lo = v - __bfloat162float(hi);
                int si = (rowh*HC + col)*ICP + ic;
                s_ah[si] = hi;
                s_al[si] = __float2bfloat16(lo);
            }
            // ---- load B fragments for this chunk (uint4-packed) ----
            {
                const uint4* wsrc = (const uint4*)(wf + (size_t)cc*9216);
                uint4* bdst = (uint4*)s_bf;
                for (int i = tid; i < 2304; i += 256)
                    bdst[i] = wsrc[i];
            }
            __syncthreads();

            // ---- compute: 9 taps, 2 m-frags sharing B regs ----
#pragma unroll 1
            for (int tap = 0; tap < 9; tap++) {
                const int dy = tap / 3, dx = tap % 3;
                uint32_t ai0 = (uint32_t)((((wid + dy)*HC) + (mm + dx))*ICP + kofs) * 2u;
                uint32_t ai1 = ai0 + (uint32_t)(16*ICP*2);
                uint32_t ah0[4], al0[4], ah1[4], al1[4];
                ldsm4(ah0, a_hi_base + ai0);
                ldsm4(al0, a_lo_base + ai0);
                ldsm4(ah1, a_hi_base + ai1);
                ldsm4(al1, a_lo_base + ai1);
#pragma unroll
                for (int nf = 0; nf < 8; nf++) {
                    uint4 bb = *(const uint4*)&s_bf[((tap*8 + nf)*32 + lane)*4];
                    mma_bf16(c[0][nf], ah0, bb.x, bb.y);
                    mma_bf16(c[1][nf], ah1, bb.x, bb.y);
                    mma_bf16(c[0][nf], ah0, bb.z, bb.w);
                    mma_bf16(c[1][nf], ah1, bb.z, bb.w);
                    mma_bf16(c[0][nf], al0, bb.x, bb.y);
                    mma_bf16(c[1][nf], al1, bb.x, bb.y);
                }
            }
        }
    }

    // ---- epilogue: two passes of 128 pixels (16-col halves) through smem ----
#pragma unroll 1
    for (int mf = 0; mf < 2; mf++) {
        __syncthreads();
        {
            int pix0 = wid*16 + (lane >> 2);
            int oc0  = (lane & 3) * 2;
#pragma unroll
            for (int nf = 0; nf < 8; nf++) {
                int oc = nf*8 + oc0;
                s_out[pix0*66 + oc]         = c[mf][nf][0];
                s_out[pix0*66 + oc + 1]     = c[mf][nf][1];
                s_out[(pix0+8)*66 + oc]     = c[mf][nf][2];
                s_out[(pix0+8)*66 + oc + 1] = c[mf][nf][3];
            }
        }
        __syncthreads();
        for (int i = tid; i < 8192; i += 256) {
            int oc = i >> 7;
            int pix = i & 127;
            float bias = b0[oc] + (b1 ? b1[oc] : 0.f);
            float v = s_out[pix*66 + oc] + bias;
            v = fmaxf(v, 0.f);
            y[((size_t)(b*Cch + oc))*HWs + (size_t)(h0 + (pix >> 4))*Ww
              + (w0c + mf*16 + (pix & 15))] = v;
        }
    }
}

// ---------------- point stage: gather + 2 MLPs + softmax + weighted sum ----
__global__ __launch_bounds__(128) void point_kernel(
    const int* __restrict__ pc, const int* __restrict__ nbrs,
    const float* __restrict__ disp,
    const float* __restrict__ d_w1, const float* __restrict__ d_b1,
    const float* __restrict__ d_w2, const float* __restrict__ d_b2,
    const float* __restrict__ r_w1, const float* __restrict__ r_b1,
    const float* __restrict__ r_w2, const float* __restrict__ r_b2,
    const float* __restrict__ d_bias, const float* __restrict__ r_bias)
{
    const int n  = blockIdx.x;
    const int b  = blockIdx.y;
    const int tid = threadIdx.x;

    __shared__ float s_ds[64], s_rs[64];
    __shared__ float s_dnn[64][9];
    __shared__ float s_feat[9][132];
    __shared__ float s_h[2][9][66];
    __shared__ float s_logit[2][9];
    __shared__ float s_attn[2][9];
    __shared__ int   s_nb[9];
    __shared__ int   s_pidx;

    if (tid == 0) s_pidx = pc[(size_t)b*NS + n];
    if (tid < Kn) s_nb[tid] = nbrs[((size_t)b*NS + n)*Kn + tid];
    __syncthreads();

    const float* d0b = g_d0 + (size_t)b * Cch * HWs;
    const float* r0b = g_r0 + (size_t)b * Cch * HWs;
    const int pidx = s_pidx;

    if (tid < 64) {
        s_ds[tid] = d0b[(size_t)tid * HWs + pidx];
        s_rs[tid] = r0b[(size_t)tid * HWs + pidx];
    }
    for (int i = tid; i < 64*Kn; i += 128) {
        int ch = i / Kn, k = i % Kn;
        s_dnn[ch][k] = d0b[(size_t)ch * HWs + s_nb[k]];
    }
    if (tid < 3*Kn) {
        int c3 = tid / Kn, k = tid % Kn;
        s_feat[k][128 + c3] = disp[(((size_t)b*3 + c3)*NS + n)*Kn + k];
    }
    __syncthreads();

    for (int i = tid; i < 64*Kn; i += 128) {
        int ch = i / Kn, k = i % Kn;
        float dn = s_dnn[ch][k];
        s_feat[k][ch]      = dn - s_ds[ch];
        s_feat[k][64 + ch] = dn - s_rs[ch];
    }
    __syncthreads();

    for (int t = tid; t < 2*Kn*Dhh; t += 128) {
        int m = t / (Kn*Dhh);
        int local = t % (Kn*Dhh);
        int k = local / Dhh;
        int j = local % Dhh;
        const float* W1 = m ? r_w1 : d_w1;
        float a = (m ? r_b1 : d_b1)[j];
#pragma unroll 1
        for (int d = 0; d < Dd; d++)
            a = fmaf(s_feat[k][d], __ldg(&W1[d*Dhh + j]), a);
        a = (a > 0.f) ? a : 0.2f * a;
        s_h[m][k][j] = a;
    }
    __syncthreads();

    if (tid < 2*Kn) {
        int m = tid / Kn, k = tid % Kn;
        const float* W2 = m ? r_w2 : d_w2;
        float a = (m ? r_b2 : d_b2)[0];
#pragma unroll 1
        for (int j = 0; j < Dhh; j++)
            a = fmaf(s_h[m][k][j], __ldg(&W2[j]), a);
        s_logit[m][k] = a;
    }
    __syncthreads();

    if (tid < 2) {
        int m = tid;
        float mx = s_logit[m][0];
#pragma unroll
        for (int k = 1; k < Kn; k++) mx = fmaxf(mx, s_logit[m][k]);
        float sum = 0.f;
        float e[Kn];
#pragma unroll
        for (int k = 0; k < Kn; k++) { e[k] = expf(s_logit[m][k] - mx); sum += e[k]; }
        float inv = 1.f / sum;
#pragma unroll
        for (int k = 0; k < Kn; k++) s_attn[m][k] = e[k] * inv;
    }
    __syncthreads();

    if (tid < 64) {
        int ch = tid;
        float a = d_bias[ch];
#pragma unroll
        for (int k = 0; k < Kn; k++) a = fmaf(s_attn[0][k], s_dnn[ch][k], a);
        g_dfeat[((size_t)b*Cch + ch)*NS + n] = a;
    } else if (tid < 128) {
        int ch = tid - 64;
        float a = r_bias[ch];
#pragma unroll
        for (int k = 0; k < Kn; k++) a = fmaf(s_attn[1][k], s_dnn[ch][k], a);
        g_rfeat[((size_t)b*Cch + ch)*NS + n] = a;
    }
}

// ---------------- scatter update (pc indices unique -> race-free) ----------
__global__ __launch_bounds__(128) void scatter_kernel(const int* __restrict__ pc)
{
    const int n = blockIdx.x;
    const int b = blockIdx.y;
    const int tid = threadIdx.x;
    const int idx = pc[(size_t)b*NS + n];

    if (tid < 64) {
        int ch = tid;
        float v = g_dfeat[((size_t)b*Cch + ch)*NS + n];
        size_t o = ((size_t)b*Cch + ch)*HWs + idx;
        g_d0[o] = (ch == 0) ? v : (g_d0[o] + v);
    } else {
        int ch = tid - 64;
        float v = g_rfeat[((size_t)b*Cch + ch)*NS + n];
        size_t o = ((size_t)b*Cch + ch)*HWs + idx;
        g_r0[o] = (ch == 0) ? v : (g_r0[o] + v);
    }
}

// ---------------------------------------------------------------------------
extern "C" void kernel_launch(void* const* d_in, const int* in_sizes, int n_in,
                              void* d_out, int out_size)
{
    const float* rgb    = (const float*)d_in[0];
    const float* sdepth = (const float*)d_in[1];
    const int*   pc     = (const int*)  d_in[2];
    const int*   nbrs   = (const int*)  d_in[3];
    const float* disp   = (const float*)d_in[4];
    const float* d_c0w  = (const float*)d_in[5];
    const float* d_c0b  = (const float*)d_in[6];
    const float* d_c1w  = (const float*)d_in[7];
    const float* d_c1b  = (const float*)d_in[8];
    const float* d_c2w  = (const float*)d_in[9];
    const float* d_c2b  = (const float*)d_in[10];
    const float* r_c0w  = (const float*)d_in[11];
    const float* r_c0b  = (const float*)d_in[12];
    const float* r_c1w  = (const float*)d_in[13];
    const float* r_c1b  = (const float*)d_in[14];
    const float* r_c2w  = (const float*)d_in[15];
    const float* r_c2b  = (const float*)d_in[16];
    const float* d_w1   = (const float*)d_in[17];
    const float* d_b1   = (const float*)d_in[18];
    const float* d_w2   = (const float*)d_in[19];
    const float* d_b2   = (const float*)d_in[20];
    const float* r_w1   = (const float*)d_in[21];
    const float* r_b1   = (const float*)d_in[22];
    const float* r_w2   = (const float*)d_in[23];
    const float* r_b2   = (const float*)d_in[24];
    const float* d_bias = (const float*)d_in[25];
    const float* r_bias = (const float*)d_in[26];
    float* out = (float*)d_out;

    float *p_gd0, *p_gr0;
    uint32_t* p_wf;
    cudaGetSymbolAddress((void**)&p_gd0, g_d0);
    cudaGetSymbolAddress((void**)&p_gr0, g_r0);
    cudaGetSymbolAddress((void**)&p_wf, g_wfrag);

    cudaFuncSetAttribute(conv3x3_mma,
                         cudaFuncAttributeMaxDynamicSharedMemorySize, SMEM_BYTES);

    // weight prepack: sets 0:d0 1:r0 2:d2 3:d1 4:r2 5:r1
    prepack_w<<<dim3(288, 6), 32>>>(d_c0w, r_c0w, d_c2w, d_c1w, r_c2w, r_c1w);

    dim3 cgrid(Ww/TC, Hh/TR, Bsz);

    // Stage A
    conv3x3_mma<<<cgrid, 256, SMEM_BYTES>>>(sdepth, p_wf + 0*WSET_U32, nullptr, nullptr,
                                            d_c0b, nullptr, p_gd0);
    conv3x3_mma<<<cgrid, 256, SMEM_BYTES>>>(rgb,    p_wf + 1*WSET_U32, nullptr, nullptr,
                                            r_c0b, nullptr, p_gr0);

    // Stage B
    point_kernel<<<dim3(NS, Bsz), 128>>>(pc, nbrs, disp,
                                         d_w1, d_b1, d_w2, d_b2,
                                         r_w1, r_b1, r_w2, r_b2,
                                         d_bias, r_bias);
    scatter_kernel<<<dim3(NS, Bsz), 128>>>(pc);

    // Stage C (fused dual-source convs)
    conv3x3_mma<<<cgrid, 256, SMEM_BYTES>>>(p_gd0, p_wf + 2*WSET_U32, sdepth, p_wf + 3*WSET_U32,
                                            d_c2b, d_c1b, out);
    conv3x3_mma<<<cgrid, 256, SMEM_BYTES>>>(p_gr0, p_wf + 4*WSET_U32, rgb, p_wf + 5*WSET_U32,
                                            r_c2b, r_c1b, out + (size_t)Bsz*Cch*HWs);
}

// round 7
// speedup vs baseline: 1.5403x; 1.4930x over previous
#include <cuda_runtime.h>
#include <cuda_bf16.h>
#include <math.h>
#include <stdint.h>

#define Bsz 2
#define Cch 64
#define Hh  256
#define Ww  1216
#define HWs (Hh*Ww)          // 311296
#define NS  20000
#define Kn  9
#define Dd  131
#define Dhh 65
#define ICP 16

// conv tile geometry (R2 proven)
#define TR 8
#define TC 16
#define HR (TR+2)            // 10
#define HC (TC+2)            // 18
#define NCELL (HR*HC)        // 180

// packed activation tensor: [cc(4)][b(2)][HW][16ch] bf16
#define PKT ((size_t)4*Bsz*HWs*16)

// ---------------- scratch (device globals) ----------------
__device__ float g_d0[(size_t)Bsz*HWs*Cch];    // NHWC fp32
__device__ float g_r0[(size_t)Bsz*HWs*Cch];    // NHWC fp32
__device__ float g_dfeat[(size_t)Bsz*Cch*NS];
__device__ float g_rfeat[(size_t)Bsz*Cch*NS];
__device__ __nv_bfloat16 g_pk_h[4*PKT];        // tensors: 0 sdepth, 1 rgb, 2 d0', 3 r0'
__device__ __nv_bfloat16 g_pk_l[4*PKT];
// packed weight frags: 6 sets x [chunk4][tap9][nf8][lane32][4u32: bh0,bh1,bl0,bl1]
#define WSET_U32 36864
__device__ uint32_t g_wfrag[6*WSET_U32];

// ---------------- helpers ----------------
__device__ __forceinline__ uint32_t pack_bf2(float a, float b) {
    __nv_bfloat162 t;
    t.x = __float2bfloat16(a);
    t.y = __float2bfloat16(b);
    return *reinterpret_cast<uint32_t*>(&t);
}

__device__ __forceinline__ void mma_bf16(float c[4], const uint32_t a[4],
                                         uint32_t b0, uint32_t b1) {
    asm volatile(
        "mma.sync.aligned.m16n8k16.row.col.f32.bf16.bf16.f32 "
        "{%0,%1,%2,%3}, {%4,%5,%6,%7}, {%8,%9}, {%0,%1,%2,%3};"
        : "+f"(c[0]), "+f"(c[1]), "+f"(c[2]), "+f"(c[3])
        : "r"(a[0]), "r"(a[1]), "r"(a[2]), "r"(a[3]), "r"(b0), "r"(b1));
}

__device__ __forceinline__ void ldsm4(uint32_t a[4], uint32_t addr) {
    asm volatile("ldmatrix.sync.aligned.m8n8.x4.shared.b16 {%0,%1,%2,%3}, [%4];"
                 : "=r"(a[0]), "=r"(a[1]), "=r"(a[2]), "=r"(a[3]) : "r"(addr));
}

// ---------------- weight prepack ----------------
__global__ void prepack_w(const float* __restrict__ w0, const float* __restrict__ w1,
                          const float* __restrict__ w2, const float* __restrict__ w3,
                          const float* __restrict__ w4, const float* __restrict__ w5)
{
    const float* w;
    switch (blockIdx.y) {
        case 0: w = w0; break; case 1: w = w1; break; case 2: w = w2; break;
        case 3: w = w3; break; case 4: w = w4; break; default: w = w5; break;
    }
    uint32_t* dst = g_wfrag + blockIdx.y * WSET_U32;

    int cb = blockIdx.x;
    int chunk = cb / 72;
    int rem = cb % 72;
    int tap = rem / 8;
    int nf = rem % 8;
    int lane = threadIdx.x;

    int oc = nf*8 + (lane >> 2);
    int k0 = (lane & 3) * 2;
    int ic = chunk*16 + k0;

    float v00 = w[oc*576 + ic*9 + tap];
    float v01 = w[oc*576 + (ic+1)*9 + tap];
    float v10 = w[oc*576 + (ic+8)*9 + tap];
    float v11 = w[oc*576 + (ic+9)*9 + tap];

    float h00 = __bfloat162float(__float2bfloat16(v00));
    float h01 = __bfloat162float(__float2bfloat16(v01));
    float h10 = __bfloat162float(__float2bfloat16(v10));
    float h11 = __bfloat162float(__float2bfloat16(v11));

    size_t base = ((((size_t)chunk*9 + tap)*8 + nf)*32 + lane)*4;
    dst[base + 0] = pack_bf2(h00, h01);
    dst[base + 1] = pack_bf2(h10, h11);
    dst[base + 2] = pack_bf2(v00 - h00, v01 - h01);
    dst[base + 3] = pack_bf2(v10 - h10, v11 - h11);
}

// ---------------- source prepack: fp32 NCHW -> packed chunk-major bf16 hi/lo --
// grid (HWs/64, Bsz), block 256. One tensor per launch.
__global__ __launch_bounds__(256) void prepack_src(
    const float* __restrict__ src, __nv_bfloat16* __restrict__ dsth,
    __nv_bfloat16* __restrict__ dstl)
{
    __shared__ float s[64][65];
    const int tid = threadIdx.x;
    const int hw0 = blockIdx.x * 64;
    const int b   = blockIdx.y;

    for (int i = tid; i < 64*64; i += 256) {
        int c = i >> 6, p = i & 63;
        s[c][p] = src[((size_t)b*64 + c)*HWs + hw0 + p];
    }
    __syncthreads();

    for (int i = tid; i < 512; i += 256) {
        int p   = i >> 3;
        int cc  = (i >> 1) & 3;
        int sub = i & 1;
        float v[8], hi[8];
        uint32_t ph[4], pl[4];
#pragma unroll
        for (int j = 0; j < 8; j++) {
            v[j] = s[cc*16 + sub*8 + j][p];
            hi[j] = __bfloat162float(__float2bfloat16(v[j]));
        }
#pragma unroll
        for (int j = 0; j < 4; j++) {
            ph[j] = pack_bf2(hi[2*j], hi[2*j+1]);
            pl[j] = pack_bf2(v[2*j] - hi[2*j], v[2*j+1] - hi[2*j+1]);
        }
        size_t o = (((size_t)cc*Bsz + b)*HWs + hw0 + p)*16 + sub*8;
        *(uint4*)&dsth[o] = make_uint4(ph[0], ph[1], ph[2], ph[3]);
        *(uint4*)&dstl[o] = make_uint4(pl[0], pl[1], pl[2], pl[3]);
    }
}

// ---------------- post-scatter split: NHWC fp32 -> packed bf16 hi/lo --------
__global__ __launch_bounds__(256) void split_feat(
    const float* __restrict__ src, __nv_bfloat16* __restrict__ dsth,
    __nv_bfloat16* __restrict__ dstl)
{
    const int tid = threadIdx.x;
    const int hw0 = blockIdx.x * 64;
    const int b   = blockIdx.y;

    for (int i = tid; i < 512; i += 256) {
        int p   = i >> 3;
        int cc  = (i >> 1) & 3;
        int sub = i & 1;
        const float* sp = src + ((size_t)b*HWs + hw0 + p)*64 + cc*16 + sub*8;
        float4 a = *(const float4*)sp;
        float4 c2 = *(const float4*)(sp + 4);
        float v[8] = {a.x, a.y, a.z, a.w, c2.x, c2.y, c2.z, c2.w};
        uint32_t ph[4], pl[4];
#pragma unroll
        for (int j = 0; j < 4; j++) {
            float h0 = __bfloat162float(__float2bfloat16(v[2*j]));
            float h1 = __bfloat162float(__float2bfloat16(v[2*j+1]));
            ph[j] = pack_bf2(h0, h1);
            pl[j] = pack_bf2(v[2*j] - h0, v[2*j+1] - h1);
        }
        size_t o = (((size_t)cc*Bsz + b)*HWs + hw0 + p)*16 + sub*8;
        *(uint4*)&dsth[o] = make_uint4(ph[0], ph[1], ph[2], ph[3]);
        *(uint4*)&dstl[o] = make_uint4(pl[0], pl[1], pl[2], pl[3]);
    }
}

// ---------------- conv 3x3 SAME via mma (split bf16), up to 2 sources ------
// Block 256 (8 warps). Tile 8 rows x 16 cols x 64 oc. Warp = 1 image row, M=16.
__global__ __launch_bounds__(256) void conv3x3_mma(
    const __nv_bfloat16* __restrict__ ph0, const __nv_bfloat16* __restrict__ pl0,
    const uint32_t* __restrict__ wf0,
    const __nv_bfloat16* __restrict__ ph1, const __nv_bfloat16* __restrict__ pl1,
    const uint32_t* __restrict__ wf1,
    const float* __restrict__ b0, const float* __restrict__ b1,
    float* __restrict__ y, int nchw_out)
{
    __shared__ __align__(16) unsigned char sraw[48384];
    __nv_bfloat16* s_ah = (__nv_bfloat16*)sraw;             // 180*16*2 = 5760B
    __nv_bfloat16* s_al = (__nv_bfloat16*)(sraw + 5760);
    uint32_t*      s_bf = (uint32_t*)(sraw + 11520);        // 9216 u32
    float*         s_out = (float*)sraw;                    // alias 128*66*4

    const int tid  = threadIdx.x;
    const int lane = tid & 31;
    const int wid  = tid >> 5;
    const int w0c  = blockIdx.x * TC;
    const int h0   = blockIdx.y * TR;
    const int b    = blockIdx.z;

    float c[8][4];
#pragma unroll
    for (int nf = 0; nf < 8; nf++)
#pragma unroll
        for (int j = 0; j < 4; j++) c[nf][j] = 0.f;

    const int mm   = lane & 15;
    const int kofs = (lane >> 4) << 3;

    uint32_t a_hi_base = (uint32_t)__cvta_generic_to_shared(s_ah);
    uint32_t a_lo_base = (uint32_t)__cvta_generic_to_shared(s_al);

#pragma unroll 1
    for (int src = 0; src < 2; src++) {
        const __nv_bfloat16* xh = src ? ph1 : ph0;
        const __nv_bfloat16* xl = src ? pl1 : pl0;
        const uint32_t* wf = src ? wf1 : wf0;
        if (xh == nullptr) break;

#pragma unroll 1
        for (int cc = 0; cc < 4; cc++) {
            __syncthreads();
            const __nv_bfloat16* bh = xh + (((size_t)cc*Bsz + b)*HWs)*16;
            const __nv_bfloat16* bl = xl + (((size_t)cc*Bsz + b)*HWs)*16;
            // ---- A fill: 180 cells x (2 hi + 2 lo) uint4 ----
            for (int j = tid; j < NCELL*4; j += 256) {
                int cell = j >> 2;
                int q    = j & 3;
                int r = cell / HC;
                int cl = cell - r*HC;
                int h = h0 - 1 + r;
                int w = w0c - 1 + cl;
                uint4 v = make_uint4(0u, 0u, 0u, 0u);
                if ((unsigned)h < (unsigned)Hh && (unsigned)w < (unsigned)Ww) {
                    const __nv_bfloat16* sp = ((q & 2) ? bl : bh)
                        + ((size_t)h*Ww + w)*16 + (q & 1)*8;
                    v = *(const uint4*)sp;
                }
                __nv_bfloat16* dp = ((q & 2) ? s_al : s_ah) + cell*16 + (q & 1)*8;
                *(uint4*)dp = v;
            }
            // ---- B fill: 2304 uint4 ----
            {
                const uint4* wsrc = (const uint4*)(wf + (size_t)cc*9216);
                uint4* bdst = (uint4*)s_bf;
                for (int i = tid; i < 2304; i += 256)
                    bdst[i] = wsrc[i];
            }
            __syncthreads();

            // ---- compute ----
#pragma unroll
            for (int tap = 0; tap < 9; tap++) {
                const int dy = tap / 3, dx = tap % 3;
                uint32_t aidx = (uint32_t)((((wid + dy)*HC) + (mm + dx))*ICP + kofs) * 2u;
                uint32_t ah[4], al[4];
                ldsm4(ah, a_hi_base + aidx);
                ldsm4(al, a_lo_base + aidx);
#pragma unroll
                for (int nf = 0; nf < 8; nf++) {
                    uint4 bb = *(const uint4*)&s_bf[((tap*8 + nf)*32 + lane)*4];
                    mma_bf16(c[nf], ah, bb.x, bb.y);
                    mma_bf16(c[nf], ah, bb.z, bb.w);
                    mma_bf16(c[nf], al, bb.x, bb.y);
                }
            }
        }
    }

    if (!nchw_out) {
        // ---- NHWC fp32 epilogue (stage A) ----
        int col0 = lane >> 2;
        size_t rowbase = ((size_t)b*HWs + (size_t)(h0 + wid)*Ww + w0c);
#pragma unroll
        for (int nf = 0; nf < 8; nf++) {
            int oc = nf*8 + (lane & 3)*2;
            float bb0 = b0[oc], bb1 = b0[oc+1];
            float2 v0, v1;
            v0.x = fmaxf(c[nf][0] + bb0, 0.f);
            v0.y = fmaxf(c[nf][1] + bb1, 0.f);
            v1.x = fmaxf(c[nf][2] + bb0, 0.f);
            v1.y = fmaxf(c[nf][3] + bb1, 0.f);
            *(float2*)&y[(rowbase + col0)*64 + oc]     = v0;
            *(float2*)&y[(rowbase + col0 + 8)*64 + oc] = v1;
        }
    } else {
        // ---- NCHW fp32 epilogue via smem transpose (stage C) ----
        __syncthreads();
        {
            int pix0 = wid*16 + (lane >> 2);
            int oc0  = (lane & 3) * 2;
#pragma unroll
            for (int nf = 0; nf < 8; nf++) {
                int oc = nf*8 + oc0;
                s_out[pix0*66 + oc]         = c[nf][0];
                s_out[pix0*66 + oc + 1]     = c[nf][1];
                s_out[(pix0+8)*66 + oc]     = c[nf][2];
                s_out[(pix0+8)*66 + oc + 1] = c[nf][3];
            }
        }
        __syncthreads();
        for (int i = tid; i < 8192; i += 256) {
            int oc = i >> 7;
            int pix = i & 127;
            float bias = b0[oc] + b1[oc];
            float v = s_out[pix*66 + oc] + bias;
            v = fmaxf(v, 0.f);
            y[((size_t)(b*Cch + oc))*HWs + (size_t)(h0 + (pix >> 4))*Ww
              + (w0c + (pix & 15))] = v;
        }
    }
}

// ---------------- point stage (NHWC gathers) ----------------
__global__ __launch_bounds__(128) void point_kernel(
    const int* __restrict__ pc, const int* __restrict__ nbrs,
    const float* __restrict__ disp,
    const float* __restrict__ d_w1, const float* __restrict__ d_b1,
    const float* __restrict__ d_w2, const float* __restrict__ d_b2,
    const float* __restrict__ r_w1, const float* __restrict__ r_b1,
    const float* __restrict__ r_w2, const float* __restrict__ r_b2,
    const float* __restrict__ d_bias, const float* __restrict__ r_bias)
{
    const int n  = blockIdx.x;
    const int b  = blockIdx.y;
    const int tid = threadIdx.x;

    __shared__ float s_ds[64], s_rs[64];
    __shared__ float s_dnn[64][9];
    __shared__ float s_feat[9][132];
    __shared__ float s_h[2][9][66];
    __shared__ float s_logit[2][9];
    __shared__ float s_attn[2][9];
    __shared__ int   s_nb[9];
    __shared__ int   s_pidx;

    if (tid == 0) s_pidx = pc[(size_t)b*NS + n];
    if (tid < Kn) s_nb[tid] = nbrs[((size_t)b*NS + n)*Kn + tid];
    __syncthreads();

    const float* d0b = g_d0 + (size_t)b * HWs * 64;
    const float* r0b = g_r0 + (size_t)b * HWs * 64;
    const int pidx = s_pidx;

    if (tid < 64) {
        s_ds[tid] = d0b[(size_t)pidx*64 + tid];
        s_rs[tid] = r0b[(size_t)pidx*64 + tid];
    }
    for (int i = tid; i < 64*Kn; i += 128) {
        int ch = i & 63, k = i >> 6;
        s_dnn[ch][k] = d0b[(size_t)s_nb[k]*64 + ch];
    }
    if (tid < 3*Kn) {
        int c3 = tid / Kn, k = tid % Kn;
        s_feat[k][128 + c3] = disp[(((size_t)b*3 + c3)*NS + n)*Kn + k];
    }
    __syncthreads();

    for (int i = tid; i < 64*Kn; i += 128) {
        int ch = i & 63, k = i >> 6;
        float dn = s_dnn[ch][k];
        s_feat[k][ch]      = dn - s_ds[ch];
        s_feat[k][64 + ch] = dn - s_rs[ch];
    }
    __syncthreads();

    for (int t = tid; t < 2*Kn*Dhh; t += 128) {
        int m = t / (Kn*Dhh);
        int local = t % (Kn*Dhh);
        int k = local / Dhh;
        int j = local % Dhh;
        const float* W1 = m ? r_w1 : d_w1;
        float a = (m ? r_b1 : d_b1)[j];
#pragma unroll 1
        for (int d = 0; d < Dd; d++)
            a = fmaf(s_feat[k][d], __ldg(&W1[d*Dhh + j]), a);
        a = (a > 0.f) ? a : 0.2f * a;
        s_h[m][k][j] = a;
    }
    __syncthreads();

    if (tid < 2*Kn) {
        int m = tid / Kn, k = tid % Kn;
        const float* W2 = m ? r_w2 : d_w2;
        float a = (m ? r_b2 : d_b2)[0];
#pragma unroll 1
        for (int j = 0; j < Dhh; j++)
            a = fmaf(s_h[m][k][j], __ldg(&W2[j]), a);
        s_logit[m][k] = a;
    }
    __syncthreads();

    if (tid < 2) {
        int m = tid;
        float mx = s_logit[m][0];
#pragma unroll
        for (int k = 1; k < Kn; k++) mx = fmaxf(mx, s_logit[m][k]);
        float sum = 0.f;
        float e[Kn];
#pragma unroll
        for (int k = 0; k < Kn; k++) { e[k] = expf(s_logit[m][k] - mx); sum += e[k]; }
        float inv = 1.f / sum;
#pragma unroll
        for (int k = 0; k < Kn; k++) s_attn[m][k] = e[k] * inv;
    }
    __syncthreads();

    if (tid < 64) {
        int ch = tid;
        float a = d_bias[ch];
#pragma unroll
        for (int k = 0; k < Kn; k++) a = fmaf(s_attn[0][k], s_dnn[ch][k], a);
        g_dfeat[((size_t)b*Cch + ch)*NS + n] = a;
    } else if (tid < 128) {
        int ch = tid - 64;
        float a = r_bias[ch];
#pragma unroll
        for (int k = 0; k < Kn; k++) a = fmaf(s_attn[1][k], s_dnn[ch][k], a);
        g_rfeat[((size_t)b*Cch + ch)*NS + n] = a;
    }
}

// ---------------- scatter (NHWC, unique pc indices) ----------------
__global__ __launch_bounds__(128) void scatter_kernel(const int* __restrict__ pc)
{
    const int n = blockIdx.x;
    const int b = blockIdx.y;
    const int tid = threadIdx.x;
    const int idx = pc[(size_t)b*NS + n];

    if (tid < 64) {
        int ch = tid;
        float v = g_dfeat[((size_t)b*Cch + ch)*NS + n];
        size_t o = ((size_t)b*HWs + idx)*64 + ch;
        g_d0[o] = (ch == 0) ? v : (g_d0[o] + v);
    } else {
        int ch = tid - 64;
        float v = g_rfeat[((size_t)b*Cch + ch)*NS + n];
        size_t o = ((size_t)b*HWs + idx)*64 + ch;
        g_r0[o] = (ch == 0) ? v : (g_r0[o] + v);
    }
}

// ---------------------------------------------------------------------------
extern "C" void kernel_launch(void* const* d_in, const int* in_sizes, int n_in,
                              void* d_out, int out_size)
{
    const float* rgb    = (const float*)d_in[0];
    const float* sdepth = (const float*)d_in[1];
    const int*   pc     = (const int*)  d_in[2];
    const int*   nbrs   = (const int*)  d_in[3];
    const float* disp   = (const float*)d_in[4];
    const float* d_c0w  = (const float*)d_in[5];
    const float* d_c0b  = (const float*)d_in[6];
    const float* d_c1w  = (const float*)d_in[7];
    const float* d_c1b  = (const float*)d_in[8];
    const float* d_c2w  = (const float*)d_in[9];
    const float* d_c2b  = (const float*)d_in[10];
    const float* r_c0w  = (const float*)d_in[11];
    const float* r_c0b  = (const float*)d_in[12];
    const float* r_c1w  = (const float*)d_in[13];
    const float* r_c1b  = (const float*)d_in[14];
    const float* r_c2w  = (const float*)d_in[15];
    const float* r_c2b  = (const float*)d_in[16];
    const float* d_w1   = (const float*)d_in[17];
    const float* d_b1   = (const float*)d_in[18];
    const float* d_w2   = (const float*)d_in[19];
    const float* d_b2   = (const float*)d_in[20];
    const float* r_w1   = (const float*)d_in[21];
    const float* r_b1   = (const float*)d_in[22];
    const float* r_w2   = (const float*)d_in[23];
    const float* r_b2   = (const float*)d_in[24];
    const float* d_bias = (const float*)d_in[25];
    const float* r_bias = (const float*)d_in[26];
    float* out = (float*)d_out;

    float *p_gd0, *p_gr0;
    uint32_t* p_wf;
    __nv_bfloat16 *p_h, *p_l;
    cudaGetSymbolAddress((void**)&p_gd0, g_d0);
    cudaGetSymbolAddress((void**)&p_gr0, g_r0);
    cudaGetSymbolAddress((void**)&p_wf, g_wfrag);
    cudaGetSymbolAddress((void**)&p_h, g_pk_h);
    cudaGetSymbolAddress((void**)&p_l, g_pk_l);

    // weight prepack: sets 0:d0 1:r0 2:d2 3:d1 4:r2 5:r1
    prepack_w<<<dim3(288, 6), 32>>>(d_c0w, r_c0w, d_c2w, d_c1w, r_c2w, r_c1w);

    dim3 pgrid(HWs/64, Bsz);
    prepack_src<<<pgrid, 256>>>(sdepth, p_h + 0*PKT, p_l + 0*PKT);
    prepack_src<<<pgrid, 256>>>(rgb,    p_h + 1*PKT, p_l + 1*PKT);

    dim3 cgrid(Ww/TC, Hh/TR, Bsz);

    // Stage A -> NHWC fp32
    conv3x3_mma<<<cgrid, 256>>>(p_h + 0*PKT, p_l + 0*PKT, p_wf + 0*WSET_U32,
                                nullptr, nullptr, nullptr,
                                d_c0b, nullptr, p_gd0, 0);
    conv3x3_mma<<<cgrid, 256>>>(p_h + 1*PKT, p_l + 1*PKT, p_wf + 1*WSET_U32,
                                nullptr, nullptr, nullptr,
                                r_c0b, nullptr, p_gr0, 0);

    // Stage B
    point_kernel<<<dim3(NS, Bsz), 128>>>(pc, nbrs, disp,
                                         d_w1, d_b1, d_w2, d_b2,
                                         r_w1, r_b1, r_w2, r_b2,
                                         d_bias, r_bias);
    scatter_kernel<<<dim3(NS, Bsz), 128>>>(pc);

    // split updated features for stage C
    split_feat<<<pgrid, 256>>>(p_gd0, p_h + 2*PKT, p_l + 2*PKT);
    split_feat<<<pgrid, 256>>>(p_gr0, p_h + 3*PKT, p_l + 3*PKT);

    // Stage C (fused dual-source) -> NCHW fp32 out
    conv3x3_mma<<<cgrid, 256>>>(p_h + 2*PKT, p_l + 2*PKT, p_wf + 2*WSET_U32,
                                p_h + 0*PKT, p_l + 0*PKT, p_wf + 3*WSET_U32,
                                d_c2b, d_c1b, out, 1);
    conv3x3_mma<<<cgrid, 256>>>(p_h + 3*PKT, p_l + 3*PKT, p_wf + 4*WSET_U32,
                                p_h + 1*PKT, p_l + 1*PKT, p_wf + 5*WSET_U32,
                                r_c2b, r_c1b, out + (size_t)Bsz*Cch*HWs, 1);
}

// round 9
// speedup vs baseline: 3.3088x; 2.1482x over previous
#include <cuda_runtime.h>
#include <cuda_bf16.h>
#include <math.h>
#include <stdint.h>

#define Bsz 2
#define Cch 64
#define Hh  256
#define Ww  1216
#define HWs (Hh*Ww)          // 311296
#define NS  20000
#define Kn  9
#define Dd  131
#define Dhh 65
#define ICP 16

// conv tile geometry
#define TR 8
#define TC 16
#define HR (TR+2)            // 10
#define HC (TC+2)            // 18
#define NCELL (HR*HC)        // 180

// packed activation tensor: [cc(4)][b(2)][HW][16ch] bf16
#define PKT ((size_t)4*Bsz*HWs*16)

// point-MLP tiling
#define NROW ((size_t)Bsz*NS*Kn)   // 360000
#define TPB  11250                 // 16-row tiles per batch (180000/16)
#define NTILE (Bsz*TPB)            // 22500

// ---------------- scratch (device globals) ----------------
__device__ float g_d0[(size_t)Bsz*HWs*Cch];    // NHWC fp32
__device__ float g_r0[(size_t)Bsz*HWs*Cch];    // NHWC fp32
__device__ float g_dfeat[(size_t)Bsz*Cch*NS];
__device__ float g_rfeat[(size_t)Bsz*Cch*NS];
__device__ __nv_bfloat16 g_pk_h[4*PKT];        // 0 sdepth, 1 rgb, 2 d0', 3 r0'
__device__ __nv_bfloat16 g_pk_l[4*PKT];
#define WSET_U32 36864
__device__ uint32_t g_wfrag[6*WSET_U32];
// point MLP: feature A-fragments [tile][chunk9][lane32][8u32: 4 hi, 4 lo]
__device__ uint32_t g_ffrag[(size_t)NTILE*9*32*8];
// MLP weight B-fragments [chunk9*nf18][lane32][4u32: bh0,bh1,bl0,bl1]
__device__ uint32_t g_mfrag[162*32*4];
__device__ float g_logd[NROW];
__device__ float g_logr[NROW];

// ---------------- helpers ----------------
__device__ __forceinline__ uint32_t pack_bf2(float a, float b) {
    __nv_bfloat162 t;
    t.x = __float2bfloat16(a);
    t.y = __float2bfloat16(b);
    return *reinterpret_cast<uint32_t*>(&t);
}

__device__ __forceinline__ void split2(float x, float y, uint32_t& hi, uint32_t& lo) {
    float hx = __bfloat162float(__float2bfloat16(x));
    float hy = __bfloat162float(__float2bfloat16(y));
    hi = pack_bf2(hx, hy);
    lo = pack_bf2(x - hx, y - hy);
}

__device__ __forceinline__ void mma_bf16(float c[4], const uint32_t a[4],
                                         uint32_t b0, uint32_t b1) {
    asm volatile(
        "mma.sync.aligned.m16n8k16.row.col.f32.bf16.bf16.f32 "
        "{%0,%1,%2,%3}, {%4,%5,%6,%7}, {%8,%9}, {%0,%1,%2,%3};"
        : "+f"(c[0]), "+f"(c[1]), "+f"(c[2]), "+f"(c[3])
        : "r"(a[0]), "r"(a[1]), "r"(a[2]), "r"(a[3]), "r"(b0), "r"(b1));
}

__device__ __forceinline__ void ldsm4(uint32_t a[4], uint32_t addr) {
    asm volatile("ldmatrix.sync.aligned.m8n8.x4.shared.b16 {%0,%1,%2,%3}, [%4];"
                 : "=r"(a[0]), "=r"(a[1]), "=r"(a[2]), "=r"(a[3]) : "r"(addr));
}

// ---------------- conv weight prepack ----------------
__global__ void prepack_w(const float* __restrict__ w0, const float* __restrict__ w1,
                          const float* __restrict__ w2, const float* __restrict__ w3,
                          const float* __restrict__ w4, const float* __restrict__ w5)
{
    const float* w;
    switch (blockIdx.y) {
        case 0: w = w0; break; case 1: w = w1; break; case 2: w = w2; break;
        case 3: w = w3; break; case 4: w = w4; break; default: w = w5; break;
    }
    uint32_t* dst = g_wfrag + blockIdx.y * WSET_U32;

    int cb = blockIdx.x;
    int chunk = cb / 72;
    int rem = cb % 72;
    int tap = rem / 8;
    int nf = rem % 8;
    int lane = threadIdx.x;

    int oc = nf*8 + (lane >> 2);
    int k0 = (lane & 3) * 2;
    int ic = chunk*16 + k0;

    float v00 = w[oc*576 + ic*9 + tap];
    float v01 = w[oc*576 + (ic+1)*9 + tap];
    float v10 = w[oc*576 + (ic+8)*9 + tap];
    float v11 = w[oc*576 + (ic+9)*9 + tap];

    size_t base = ((((size_t)chunk*9 + tap)*8 + nf)*32 + lane)*4;
    uint32_t h0, l0, h1, l1;
    split2(v00, v01, h0, l0);
    split2(v10, v11, h1, l1);
    dst[base + 0] = h0;
    dst[base + 1] = h1;
    dst[base + 2] = l0;
    dst[base + 3] = l1;
}

// ---------------- MLP weight prepack: B-frags for N=144 (d|r) ----------------
__global__ void prepack_mlp(const float* __restrict__ dw1, const float* __restrict__ rw1)
{
    int cb = blockIdx.x;            // chunk*18 + nf
    int chunk = cb / 18, nf = cb % 18;
    int lane = threadIdx.x;
    int jl = lane >> 2;
    int kq = 2*(lane & 3);
    const float* W;
    int j;
    if (nf < 9) { W = dw1; j = nf*8 + jl; }
    else        { W = rw1; j = (nf-9)*8 + jl; }
    bool jv = (j < Dhh);
    int k0 = chunk*16 + kq;
    float v0 = (jv && k0   < Dd) ? W[(k0  )*Dhh + j] : 0.f;
    float v1 = (jv && k0+1 < Dd) ? W[(k0+1)*Dhh + j] : 0.f;
    float v2 = (jv && k0+8 < Dd) ? W[(k0+8)*Dhh + j] : 0.f;
    float v3 = (jv && k0+9 < Dd) ? W[(k0+9)*Dhh + j] : 0.f;
    uint32_t h0, l0, h1, l1;
    split2(v0, v1, h0, l0);
    split2(v2, v3, h1, l1);
    *(uint4*)&g_mfrag[((size_t)cb*32 + lane)*4] = make_uint4(h0, h1, l0, l1);
}

// ---------------- source prepack: fp32 NCHW -> packed chunk-major bf16 hi/lo --
__global__ __launch_bounds__(256) void prepack_src(
    const float* __restrict__ src, __nv_bfloat16* __restrict__ dsth,
    __nv_bfloat16* __restrict__ dstl)
{
    __shared__ float s[64][65];
    const int tid = threadIdx.x;
    const int hw0 = blockIdx.x * 64;
    const int b   = blockIdx.y;

    for (int i = tid; i < 64*64; i += 256) {
        int c = i >> 6, p = i & 63;
        s[c][p] = src[((size_t)b*64 + c)*HWs + hw0 + p];
    }
    __syncthreads();

    for (int i = tid; i < 512; i += 256) {
        int p   = i >> 3;
        int cc  = (i >> 1) & 3;
        int sub = i & 1;
        uint32_t ph[4], pl[4];
#pragma unroll
        for (int j = 0; j < 4; j++)
            split2(s[cc*16 + sub*8 + 2*j][p], s[cc*16 + sub*8 + 2*j+1][p], ph[j], pl[j]);
        size_t o = (((size_t)cc*Bsz + b)*HWs + hw0 + p)*16 + sub*8;
        *(uint4*)&dsth[o] = make_uint4(ph[0], ph[1], ph[2], ph[3]);
        *(uint4*)&dstl[o] = make_uint4(pl[0], pl[1], pl[2], pl[3]);
    }
}

// ---------------- post-scatter split: NHWC fp32 -> packed bf16 hi/lo --------
__global__ __launch_bounds__(256) void split_feat(
    const float* __restrict__ src, __nv_bfloat16* __restrict__ dsth,
    __nv_bfloat16* __restrict__ dstl)
{
    const int tid = threadIdx.x;
    const int hw0 = blockIdx.x * 64;
    const int b   = blockIdx.y;

    for (int i = tid; i < 512; i += 256) {
        int p   = i >> 3;
        int cc  = (i >> 1) & 3;
        int sub = i & 1;
        const float* sp = src + ((size_t)b*HWs + hw0 + p)*64 + cc*16 + sub*8;
        float4 a = *(const float4*)sp;
        float4 c2 = *(const float4*)(sp + 4);
        float v[8] = {a.x, a.y, a.z, a.w, c2.x, c2.y, c2.z, c2.w};
        uint32_t ph[4], pl[4];
#pragma unroll
        for (int j = 0; j < 4; j++)
            split2(v[2*j], v[2*j+1], ph[j], pl[j]);
        size_t o = (((size_t)cc*Bsz + b)*HWs + hw0 + p)*16 + sub*8;
        *(uint4*)&dsth[o] = make_uint4(ph[0], ph[1], ph[2], ph[3]);
        *(uint4*)&dstl[o] = make_uint4(pl[0], pl[1], pl[2], pl[3]);
    }
}

// ---------------- conv 3x3 SAME via mma (split bf16), up to 2 sources ------
__global__ __launch_bounds__(256) void conv3x3_mma(
    const __nv_bfloat16* __restrict__ ph0, const __nv_bfloat16* __restrict__ pl0,
    const uint32_t* __restrict__ wf0,
    const __nv_bfloat16* __restrict__ ph1, const __nv_bfloat16* __restrict__ pl1,
    const uint32_t* __restrict__ wf1,
    const float* __restrict__ b0, const float* __restrict__ b1,
    float* __restrict__ y, int nchw_out)
{
    __shared__ __align__(16) unsigned char sraw[48384];
    __nv_bfloat16* s_ah = (__nv_bfloat16*)sraw;
    __nv_bfloat16* s_al = (__nv_bfloat16*)(sraw + 5760);
    uint32_t*      s_bf = (uint32_t*)(sraw + 11520);
    float*         s_out = (float*)sraw;

    const int tid  = threadIdx.x;
    const int lane = tid & 31;
    const int wid  = tid >> 5;
    const int w0c  = blockIdx.x * TC;
    const int h0   = blockIdx.y * TR;
    const int b    = blockIdx.z;

    float c[8][4];
#pragma unroll
    for (int nf = 0; nf < 8; nf++)
#pragma unroll
        for (int j = 0; j < 4; j++) c[nf][j] = 0.f;

    const int mm   = lane & 15;
    const int kofs = (lane >> 4) << 3;

    uint32_t a_hi_base = (uint32_t)__cvta_generic_to_shared(s_ah);
    uint32_t a_lo_base = (uint32_t)__cvta_generic_to_shared(s_al);

#pragma unroll 1
    for (int src = 0; src < 2; src++) {
        const __nv_bfloat16* xh = src ? ph1 : ph0;
        const __nv_bfloat16* xl = src ? pl1 : pl0;
        const uint32_t* wf = src ? wf1 : wf0;
        if (xh == nullptr) break;

#pragma unroll 1
        for (int cc = 0; cc < 4; cc++) {
            __syncthreads();
            const __nv_bfloat16* bh = xh + (((size_t)cc*Bsz + b)*HWs)*16;
            const __nv_bfloat16* bl = xl + (((size_t)cc*Bsz + b)*HWs)*16;
            for (int j = tid; j < NCELL*4; j += 256) {
                int cell = j >> 2;
                int q    = j & 3;
                int r = cell / HC;
                int cl = cell - r*HC;
                int h = h0 - 1 + r;
                int w = w0c - 1 + cl;
                uint4 v = make_uint4(0u, 0u, 0u, 0u);
                if ((unsigned)h < (unsigned)Hh && (unsigned)w < (unsigned)Ww) {
                    const __nv_bfloat16* sp = ((q & 2) ? bl : bh)
                        + ((size_t)h*Ww + w)*16 + (q & 1)*8;
                    v = *(const uint4*)sp;
                }
                __nv_bfloat16* dp = ((q & 2) ? s_al : s_ah) + cell*16 + (q & 1)*8;
                *(uint4*)dp = v;
            }
            {
                const uint4* wsrc = (const uint4*)(wf + (size_t)cc*9216);
                uint4* bdst = (uint4*)s_bf;
                for (int i = tid; i < 2304; i += 256)
                    bdst[i] = wsrc[i];
            }
            __syncthreads();

#pragma unroll
            for (int tap = 0; tap < 9; tap++) {
                const int dy = tap / 3, dx = tap % 3;
                uint32_t aidx = (uint32_t)((((wid + dy)*HC) + (mm + dx))*ICP + kofs) * 2u;
                uint32_t ah[4], al[4];
                ldsm4(ah, a_hi_base + aidx);
                ldsm4(al, a_lo_base + aidx);
#pragma unroll
                for (int nf = 0; nf < 8; nf++) {
                    uint4 bb = *(const uint4*)&s_bf[((tap*8 + nf)*32 + lane)*4];
                    mma_bf16(c[nf], ah, bb.x, bb.y);
                    mma_bf16(c[nf], ah, bb.z, bb.w);
                    mma_bf16(c[nf], al, bb.x, bb.y);
                }
            }
        }
    }

    if (!nchw_out) {
        int col0 = lane >> 2;
        size_t rowbase = ((size_t)b*HWs + (size_t)(h0 + wid)*Ww + w0c);
#pragma unroll
        for (int nf = 0; nf < 8; nf++) {
            int oc = nf*8 + (lane & 3)*2;
            float bb0 = b0[oc], bb1 = b0[oc+1];
            float2 v0, v1;
            v0.x = fmaxf(c[nf][0] + bb0, 0.f);
            v0.y = fmaxf(c[nf][1] + bb1, 0.f);
            v1.x = fmaxf(c[nf][2] + bb0, 0.f);
            v1.y = fmaxf(c[nf][3] + bb1, 0.f);
            *(float2*)&y[(rowbase + col0)*64 + oc]     = v0;
            *(float2*)&y[(rowbase + col0 + 8)*64 + oc] = v1;
        }
    } else {
        __syncthreads();
        {
            int pix0 = wid*16 + (lane >> 2);
            int oc0  = (lane & 3) * 2;
#pragma unroll
            for (int nf = 0; nf < 8; nf++) {
                int oc = nf*8 + oc0;
                s_out[pix0*66 + oc]         = c[nf][0];
                s_out[pix0*66 + oc + 1]     = c[nf][1];
                s_out[(pix0+8)*66 + oc]     = c[nf][2];
                s_out[(pix0+8)*66 + oc + 1] = c[nf][3];
            }
        }
        __syncthreads();
        for (int i = tid; i < 8192; i += 256) {
            int oc = i >> 7;
            int pix = i & 127;
            float bias = b0[oc] + b1[oc];
            float v = s_out[pix*66 + oc] + bias;
            v = fmaxf(v, 0.f);
            y[((size_t)(b*Cch + oc))*HWs + (size_t)(h0 + (pix >> 4))*Ww
              + (w0c + (pix & 15))] = v;
        }
    }
}

// ---------------- P1: build feature A-fragments (hi/lo bf16) ---------------
// warp = one 16-row tile (rows = flattened (n,k) per batch). grid warps = NTILE.
__global__ __launch_bounds__(256) void build_feat(
    const int* __restrict__ pc, const int* __restrict__ nbrs,
    const float* __restrict__ disp)
{
    int gw = (blockIdx.x*256 + threadIdx.x) >> 5;
    if (gw >= NTILE) return;
    int lane = threadIdx.x & 31;
    int b = gw / TPB;
    int row0 = (gw - b*TPB) * 16;
    int q = lane & 3;
    int r1 = lane >> 2;
    int rw1 = row0 + r1, rw2 = rw1 + 8;
    int n1 = rw1/9, k1 = rw1 - n1*9;
    int n2 = rw2/9, k2 = rw2 - n2*9;
    int nb1 = nbrs[((size_t)b*NS + n1)*Kn + k1];
    int nb2 = nbrs[((size_t)b*NS + n2)*Kn + k2];
    int p1 = pc[(size_t)b*NS + n1];
    int p2 = pc[(size_t)b*NS + n2];
    const float* d0b = g_d0 + (size_t)b*HWs*64;
    const float* r0b = g_r0 + (size_t)b*HWs*64;
    uint32_t* dst0 = g_ffrag + (((size_t)gw*9)*32 + lane)*8;

#pragma unroll
    for (int dc = 0; dc < 4; dc++) {
        int cA = dc*16 + 2*q, cB = cA + 8;
        float2 nA1 = *(const float2*)&d0b[(size_t)nb1*64 + cA];
        float2 nB1 = *(const float2*)&d0b[(size_t)nb1*64 + cB];
        float2 nA2 = *(const float2*)&d0b[(size_t)nb2*64 + cA];
        float2 nB2 = *(const float2*)&d0b[(size_t)nb2*64 + cB];
        float2 dA1 = *(const float2*)&d0b[(size_t)p1*64 + cA];
        float2 dB1 = *(const float2*)&d0b[(size_t)p1*64 + cB];
        float2 dA2 = *(const float2*)&d0b[(size_t)p2*64 + cA];
        float2 dB2 = *(const float2*)&d0b[(size_t)p2*64 + cB];
        float2 rA1 = *(const float2*)&r0b[(size_t)p1*64 + cA];
        float2 rB1 = *(const float2*)&r0b[(size_t)p1*64 + cB];
        float2 rA2 = *(const float2*)&r0b[(size_t)p2*64 + cA];
        float2 rB2 = *(const float2*)&r0b[(size_t)p2*64 + cB];

        uint32_t h0,h1,h2,h3,l0,l1,l2,l3;
        // chunk dc: d_nn - d_s
        split2(nA1.x - dA1.x, nA1.y - dA1.y, h0, l0);
        split2(nA2.x - dA2.x, nA2.y - dA2.y, h1, l1);
        split2(nB1.x - dB1.x, nB1.y - dB1.y, h2, l2);
        split2(nB2.x - dB2.x, nB2.y - dB2.y, h3, l3);
        uint32_t* d1 = dst0 + (size_t)dc*32*8;
        *(uint4*)(d1)     = make_uint4(h0, h1, h2, h3);
        *(uint4*)(d1 + 4) = make_uint4(l0, l1, l2, l3);
        // chunk dc+4: d_nn - r_s  (r-neighbors gathered from d0, faithful)
        split2(nA1.x - rA1.x, nA1.y - rA1.y, h0, l0);
        split2(nA2.x - rA2.x, nA2.y - rA2.y, h1, l1);
        split2(nB1.x - rB1.x, nB1.y - rB1.y, h2, l2);
        split2(nB2.x - rB2.x, nB2.y - rB2.y, h3, l3);
        uint32_t* d2 = dst0 + (size_t)(dc+4)*32*8;
        *(uint4*)(d2)     = make_uint4(h0, h1, h2, h3);
        *(uint4*)(d2 + 4) = make_uint4(l0, l1, l2, l3);
    }
    // chunk 8: disp dims 128..130, rest zero
    {
        float v0a = 0.f, v0b = 0.f, v1a = 0.f, v1b = 0.f;
        if (q == 0) {
            v0a = disp[(((size_t)b*3+0)*NS + n1)*Kn + k1];
            v0b = disp[(((size_t)b*3+1)*NS + n1)*Kn + k1];
            v1a = disp[(((size_t)b*3+0)*NS + n2)*Kn + k2];
            v1b = disp[(((size_t)b*3+1)*NS + n2)*Kn + k2];
        } else if (q == 1) {
            v0a = disp[(((size_t)b*3+2)*NS + n1)*Kn + k1];
            v1a = disp[(((size_t)b*3+2)*NS + n2)*Kn + k2];
        }
        uint32_t h0,h1,l0,l1;
        split2(v0a, v0b, h0, l0);
        split2(v1a, v1b, h1, l1);
        uint32_t* d8 = dst0 + (size_t)8*32*8;
        *(uint4*)(d8)     = make_uint4(h0, h1, 0u, 0u);
        *(uint4*)(d8 + 4) = make_uint4(l0, l1, 0u, 0u);
    }
}

// ---------------- P2: fused dual-MLP GEMM + layer2 -> logits ---------------
// block 256 = 8 warps, warp = one 16-row tile, N=144 (d:0-71, r:72-143), K=144.
__global__ __launch_bounds__(256) void mlp_gemm(
    const float* __restrict__ db1, const float* __restrict__ rb1,
    const float* __restrict__ dw2, const float* __restrict__ rw2)
{
    extern __shared__ uint32_t s_b[];    // 20736 u32 = 82944 B
    const int tid  = threadIdx.x;
    const int lane = tid & 31;
    const int w    = tid >> 5;

    {
        const uint4* src = (const uint4*)g_mfrag;
        uint4* dst = (uint4*)s_b;
        for (int i = tid; i < 5184; i += 256) dst[i] = src[i];
    }
    __syncthreads();

    int t = blockIdx.x*8 + w;
    if (t >= NTILE) return;

    float c[18][4];
#pragma unroll
    for (int nf = 0; nf < 18; nf++)
#pragma unroll
        for (int j = 0; j < 4; j++) c[nf][j] = 0.f;

    const uint4* af = (const uint4*)g_ffrag;
#pragma unroll 1
    for (int chunk = 0; chunk < 9; chunk++) {
        size_t ai = (((size_t)t*9 + chunk)*32 + lane)*2;
        uint4 ahv = af[ai];
        uint4 alv = af[ai + 1];
        uint32_t ah[4] = {ahv.x, ahv.y, ahv.z, ahv.w};
        uint32_t al[4] = {alv.x, alv.y, alv.z, alv.w};
#pragma unroll
        for (int nf = 0; nf < 18; nf++) {
            uint4 bb = *(const uint4*)&s_b[((chunk*18 + nf)*32 + lane)*4];
            mma_bf16(c[nf], ah, bb.x, bb.y);
            mma_bf16(c[nf], ah, bb.z, bb.w);
            mma_bf16(c[nf], al, bb.x, bb.y);
        }
    }

    // epilogue: bias + leaky relu + dot(w2), reduce over quad
    float sd1 = 0.f, sd2 = 0.f, sr1 = 0.f, sr2 = 0.f;
    int ocq = (lane & 3)*2;
#pragma unroll
    for (int nf = 0; nf < 18; nf++) {
        int jj = (nf < 9) ? (nf*8 + ocq) : ((nf-9)*8 + ocq);
        const float* B1 = (nf < 9) ? db1 : rb1;
        const float* W2 = (nf < 9) ? dw2 : rw2;
        float bb0 = (jj   < Dhh) ? B1[jj]   : 0.f;
        float bb1 = (jj+1 < Dhh) ? B1[jj+1] : 0.f;
        float w20 = (jj   < Dhh) ? W2[jj]   : 0.f;
        float w21 = (jj+1 < Dhh) ? W2[jj+1] : 0.f;
        float h0 = c[nf][0] + bb0; h0 = (h0 > 0.f) ? h0 : 0.2f*h0;
        float h1 = c[nf][1] + bb1; h1 = (h1 > 0.f) ? h1 : 0.2f*h1;
        float h2 = c[nf][2] + bb0; h2 = (h2 > 0.f) ? h2 : 0.2f*h2;
        float h3 = c[nf][3] + bb1; h3 = (h3 > 0.f) ? h3 : 0.2f*h3;
        float s1 = h0*w20 + h1*w21;
        float s2 = h2*w20 + h3*w21;
        if (nf < 9) { sd1 += s1; sd2 += s2; }
        else        { sr1 += s1; sr2 += s2; }
    }
#pragma unroll
    for (int d = 1; d <= 2; d <<= 1) {
        sd1 += __shfl_xor_sync(0xffffffffu, sd1, d);
        sd2 += __shfl_xor_sync(0xffffffffu, sd2, d);
        sr1 += __shfl_xor_sync(0xffffffffu, sr1, d);
        sr2 += __shfl_xor_sync(0xffffffffu, sr2, d);
    }
    if ((lane & 3) == 0) {
        size_t row = (size_t)t*16 + (lane >> 2);
        g_logd[row]     = sd1;
        g_logd[row + 8] = sd2;
        g_logr[row]     = sr1;
        g_logr[row + 8] = sr2;
    }
}

// ---------------- P3: softmax + weighted neighbor sum ----------------------
__global__ __launch_bounds__(64) void point_softmax(
    const int* __restrict__ nbrs,
    const float* __restrict__ d_bias, const float* __restrict__ r_bias)
{
    const int n = blockIdx.x;
    const int b = blockIdx.y;
    const int tid = threadIdx.x;
    __shared__ int s_nb[9];
    if (tid < Kn) s_nb[tid] = nbrs[((size_t)b*NS + n)*Kn + tid];
    __syncthreads();

    size_t base = ((size_t)b*NS + n)*Kn;
    float ld[9], lr[9];
    float mxd = -1e30f, mxr = -1e30f;
#pragma unroll
    for (int k = 0; k < Kn; k++) {
        ld[k] = g_logd[base + k];
        lr[k] = g_logr[base + k];
        mxd = fmaxf(mxd, ld[k]);
        mxr = fmaxf(mxr, lr[k]);
    }
    float sd = 0.f, sr = 0.f;
#pragma unroll
    for (int k = 0; k < Kn; k++) {
        ld[k] = expf(ld[k] - mxd); sd += ld[k];
        lr[k] = expf(lr[k] - mxr); sr += lr[k];
    }
    float invd = 1.f/sd, invr = 1.f/sr;
#pragma unroll
    for (int k = 0; k < Kn; k++) { ld[k] *= invd; lr[k] *= invr; }

    const float* d0b = g_d0 + (size_t)b*HWs*64;
    int ch = tid;
    float ad = d_bias[ch], ar = r_bias[ch];
#pragma unroll
    for (int k = 0; k < Kn; k++) {
        float dn = d0b[(size_t)s_nb[k]*64 + ch];
        ad = fmaf(ld[k], dn, ad);
        ar = fmaf(lr[k], dn, ar);
    }
    g_dfeat[((size_t)b*Cch + ch)*NS + n] = ad;
    g_rfeat[((size_t)b*Cch + ch)*NS + n] = ar;
}

// ---------------- scatter (NHWC, unique pc indices) ----------------
__global__ __launch_bounds__(128) void scatter_kernel(const int* __restrict__ pc)
{
    const int n = blockIdx.x;
    const int b = blockIdx.y;
    const int tid = threadIdx.x;
    const int idx = pc[(size_t)b*NS + n];

    if (tid < 64) {
        int ch = tid;
        float v = g_dfeat[((size_t)b*Cch + ch)*NS + n];
        size_t o = ((size_t)b*HWs + idx)*64 + ch;
        g_d0[o] = (ch == 0) ? v : (g_d0[o] + v);
    } else {
        int ch = tid - 64;
        float v = g_rfeat[((size_t)b*Cch + ch)*NS + n];
        size_t o = ((size_t)b*HWs + idx)*64 + ch;
        g_r0[o] = (ch == 0) ? v : (g_r0[o] + v);
    }
}

// ---------------------------------------------------------------------------
extern "C" void kernel_launch(void* const* d_in, const int* in_sizes, int n_in,
                              void* d_out, int out_size)
{
    const float* rgb    = (const float*)d_in[0];
    const float* sdepth = (const float*)d_in[1];
    const int*   pc     = (const int*)  d_in[2];
    const int*   nbrs   = (const int*)  d_in[3];
    const float* disp   = (const float*)d_in[4];
    const float* d_c0w  = (const float*)d_in[5];
    const float* d_c0b  = (const float*)d_in[6];
    const float* d_c1w  = (const float*)d_in[7];
    const float* d_c1b  = (const float*)d_in[8];
    const float* d_c2w  = (const float*)d_in[9];
    const float* d_c2b  = (const float*)d_in[10];
    const float* r_c0w  = (const float*)d_in[11];
    const float* r_c0b  = (const float*)d_in[12];
    const float* r_c1w  = (const float*)d_in[13];
    const float* r_c1b  = (const float*)d_in[14];
    const float* r_c2w  = (const float*)d_in[15];
    const float* r_c2b  = (const float*)d_in[16];
    const float* d_w1   = (const float*)d_in[17];
    const float* d_b1   = (const float*)d_in[18];
    const float* d_w2   = (const float*)d_in[19];
    const float* d_b2   = (const float*)d_in[20];
    const float* r_w1   = (const float*)d_in[21];
    const float* r_b1   = (const float*)d_in[22];
    const float* r_w2   = (const float*)d_in[23];
    const float* r_b2   = (const float*)d_in[24];
    const float* d_bias = (const float*)d_in[25];
    const float* r_bias = (const float*)d_in[26];
    float* out = (float*)d_out;
    (void)d_b2; (void)r_b2;   // softmax is shift-invariant

    float *p_gd0, *p_gr0;
    uint32_t* p_wf;
    __nv_bfloat16 *p_h, *p_l;
    cudaGetSymbolAddress((void**)&p_gd0, g_d0);
    cudaGetSymbolAddress((void**)&p_gr0, g_r0);
    cudaGetSymbolAddress((void**)&p_wf, g_wfrag);
    cudaGetSymbolAddress((void**)&p_h, g_pk_h);
    cudaGetSymbolAddress((void**)&p_l, g_pk_l);

    cudaFuncSetAttribute(mlp_gemm,
                         cudaFuncAttributeMaxDynamicSharedMemorySize, 82944);

    // weight prepacks
    prepack_w<<<dim3(288, 6), 32>>>(d_c0w, r_c0w, d_c2w, d_c1w, r_c2w, r_c1w);
    prepack_mlp<<<162, 32>>>(d_w1, r_w1);

    dim3 pgrid(HWs/64, Bsz);
    prepack_src<<<pgrid, 256>>>(sdepth, p_h + 0*PKT, p_l + 0*PKT);
    prepack_src<<<pgrid, 256>>>(rgb,    p_h + 1*PKT, p_l + 1*PKT);

    dim3 cgrid(Ww/TC, Hh/TR, Bsz);

    // Stage A -> NHWC fp32
    conv3x3_mma<<<cgrid, 256>>>(p_h + 0*PKT, p_l + 0*PKT, p_wf + 0*WSET_U32,
                                nullptr, nullptr, nullptr,
                                d_c0b, nullptr, p_gd0, 0);
    conv3x3_mma<<<cgrid, 256>>>(p_h + 1*PKT, p_l + 1*PKT, p_wf + 1*WSET_U32,
                                nullptr, nullptr, nullptr,
                                r_c0b, nullptr, p_gr0, 0);

    // Stage B: tensorized point MLP
    build_feat<<<(NTILE*32 + 255)/256, 256>>>(pc, nbrs, disp);
    mlp_gemm<<<(NTILE + 7)/8, 256, 82944>>>(d_b1, r_b1, d_w2, r_w2);
    point_softmax<<<dim3(NS, Bsz), 64>>>(nbrs, d_bias, r_bias);
    scatter_kernel<<<dim3(NS, Bsz), 128>>>(pc);

    // split updated features for stage C
    split_feat<<<pgrid, 256>>>(p_gd0, p_h + 2*PKT, p_l + 2*PKT);
    split_feat<<<pgrid, 256>>>(p_gr0, p_h + 3*PKT, p_l + 3*PKT);

    // Stage C (fused dual-source) -> NCHW fp32 out
    conv3x3_mma<<<cgrid, 256>>>(p_h + 2*PKT, p_l + 2*PKT, p_wf + 2*WSET_U32,
                                p_h + 0*PKT, p_l + 0*PKT, p_wf + 3*WSET_U32,
                                d_c2b, d_c1b, out, 1);
    conv3x3_mma<<<cgrid, 256>>>(p_h + 3*PKT, p_l + 3*PKT, p_wf + 4*WSET_U32,
                                p_h + 1*PKT, p_l + 1*PKT, p_wf + 5*WSET_U32,
                                r_c2b, r_c1b, out + (size_t)Bsz*Cch*HWs, 1);
}

// round 10
// speedup vs baseline: 3.9970x; 1.2080x over previous
#include <cuda_runtime.h>
#include <cuda_bf16.h>
#include <math.h>
#include <stdint.h>

#define Bsz 2
#define Cch 64
#define Hh  256
#define Ww  1216
#define HWs (Hh*Ww)          // 311296
#define NS  20000
#define Kn  9
#define Dd  131
#define Dhh 65
#define ICP 16

// conv tile geometry
#define TR 8
#define TC 16
#define HR (TR+2)            // 10
#define HC (TC+2)            // 18
#define NCELL (HR*HC)        // 180

// per-stage smem buffer: ah 5760 + al 5760 + B 36864 = 48384
#define BUFB 48384
#define SMEM_CONV (2*BUFB)   // 96768

// packed activation tensor: [cc(4)][b(2)][HW][16ch] bf16
#define PKT ((size_t)4*Bsz*HWs*16)

// point-MLP tiling
#define NROW ((size_t)Bsz*NS*Kn)   // 360000
#define TPB  11250
#define NTILE (Bsz*TPB)            // 22500

// ---------------- scratch (device globals) ----------------
__device__ float g_d0[(size_t)Bsz*HWs*Cch];    // NHWC fp32
__device__ float g_r0[(size_t)Bsz*HWs*Cch];    // NHWC fp32
__device__ float g_dfeat[(size_t)Bsz*Cch*NS];
__device__ float g_rfeat[(size_t)Bsz*Cch*NS];
__device__ __nv_bfloat16 g_pk_h[4*PKT];        // 0 sdepth, 1 rgb, 2 d0', 3 r0'
__device__ __nv_bfloat16 g_pk_l[4*PKT];
#define WSET_U32 36864
__device__ uint32_t g_wfrag[6*WSET_U32];
__device__ uint32_t g_ffrag[(size_t)NTILE*9*32*8];
__device__ uint32_t g_mfrag[162*32*4];
__device__ float g_logd[NROW];
__device__ float g_logr[NROW];

// ---------------- helpers ----------------
#define CP16(dst, src, sz) \
    asm volatile("cp.async.cg.shared.global [%0], [%1], 16, %2;\n" \
                 :: "r"(dst), "l"(src), "r"(sz))
#define CPCOMMIT() asm volatile("cp.async.commit_group;\n")
#define CPWAIT(N)  asm volatile("cp.async.wait_group %0;\n" :: "n"(N))

__device__ __forceinline__ uint32_t pack_bf2(float a, float b) {
    __nv_bfloat162 t;
    t.x = __float2bfloat16(a);
    t.y = __float2bfloat16(b);
    return *reinterpret_cast<uint32_t*>(&t);
}

__device__ __forceinline__ void split2(float x, float y, uint32_t& hi, uint32_t& lo) {
    float hx = __bfloat162float(__float2bfloat16(x));
    float hy = __bfloat162float(__float2bfloat16(y));
    hi = pack_bf2(hx, hy);
    lo = pack_bf2(x - hx, y - hy);
}

__device__ __forceinline__ void mma_bf16(float c[4], const uint32_t a[4],
                                         uint32_t b0, uint32_t b1) {
    asm volatile(
        "mma.sync.aligned.m16n8k16.row.col.f32.bf16.bf16.f32 "
        "{%0,%1,%2,%3}, {%4,%5,%6,%7}, {%8,%9}, {%0,%1,%2,%3};"
        : "+f"(c[0]), "+f"(c[1]), "+f"(c[2]), "+f"(c[3])
        : "r"(a[0]), "r"(a[1]), "r"(a[2]), "r"(a[3]), "r"(b0), "r"(b1));
}

__device__ __forceinline__ void ldsm4(uint32_t a[4], uint32_t addr) {
    asm volatile("ldmatrix.sync.aligned.m8n8.x4.shared.b16 {%0,%1,%2,%3}, [%4];"
                 : "=r"(a[0]), "=r"(a[1]), "=r"(a[2]), "=r"(a[3]) : "r"(addr));
}

// ---------------- conv weight prepack ----------------
__global__ void prepack_w(const float* __restrict__ w0, const float* __restrict__ w1,
                          const float* __restrict__ w2, const float* __restrict__ w3,
                          const float* __restrict__ w4, const float* __restrict__ w5)
{
    const float* w;
    switch (blockIdx.y) {
        case 0: w = w0; break; case 1: w = w1; break; case 2: w = w2; break;
        case 3: w = w3; break; case 4: w = w4; break; default: w = w5; break;
    }
    uint32_t* dst = g_wfrag + blockIdx.y * WSET_U32;

    int cb = blockIdx.x;
    int chunk = cb / 72;
    int rem = cb % 72;
    int tap = rem / 8;
    int nf = rem % 8;
    int lane = threadIdx.x;

    int oc = nf*8 + (lane >> 2);
    int k0 = (lane & 3) * 2;
    int ic = chunk*16 + k0;

    float v00 = w[oc*576 + ic*9 + tap];
    float v01 = w[oc*576 + (ic+1)*9 + tap];
    float v10 = w[oc*576 + (ic+8)*9 + tap];
    float v11 = w[oc*576 + (ic+9)*9 + tap];

    size_t base = ((((size_t)chunk*9 + tap)*8 + nf)*32 + lane)*4;
    uint32_t h0, l0, h1, l1;
    split2(v00, v01, h0, l0);
    split2(v10, v11, h1, l1);
    dst[base + 0] = h0;
    dst[base + 1] = h1;
    dst[base + 2] = l0;
    dst[base + 3] = l1;
}

// ---------------- MLP weight prepack ----------------
__global__ void prepack_mlp(const float* __restrict__ dw1, const float* __restrict__ rw1)
{
    int cb = blockIdx.x;
    int chunk = cb / 18, nf = cb % 18;
    int lane = threadIdx.x;
    int jl = lane >> 2;
    int kq = 2*(lane & 3);
    const float* W;
    int j;
    if (nf < 9) { W = dw1; j = nf*8 + jl; }
    else        { W = rw1; j = (nf-9)*8 + jl; }
    bool jv = (j < Dhh);
    int k0 = chunk*16 + kq;
    float v0 = (jv && k0   < Dd) ? W[(k0  )*Dhh + j] : 0.f;
    float v1 = (jv && k0+1 < Dd) ? W[(k0+1)*Dhh + j] : 0.f;
    float v2 = (jv && k0+8 < Dd) ? W[(k0+8)*Dhh + j] : 0.f;
    float v3 = (jv && k0+9 < Dd) ? W[(k0+9)*Dhh + j] : 0.f;
    uint32_t h0, l0, h1, l1;
    split2(v0, v1, h0, l0);
    split2(v2, v3, h1, l1);
    *(uint4*)&g_mfrag[((size_t)cb*32 + lane)*4] = make_uint4(h0, h1, l0, l1);
}

// ---------------- source prepack: NCHW fp32 -> packed bf16 hi/lo -----------
// grid (HWs/64, 2*Bsz): y&1 = set (0 sdepth, 1 rgb), y>>1 = b.
__global__ __launch_bounds__(256) void prepack_src(
    const float* __restrict__ sdepth, const float* __restrict__ rgb)
{
    __shared__ float s[64][65];
    const int tid = threadIdx.x;
    const int hw0 = blockIdx.x * 64;
    const int set = blockIdx.y & 1;
    const int b   = blockIdx.y >> 1;
    const float* src = set ? rgb : sdepth;
    __nv_bfloat16* dsth = g_pk_h + (size_t)set*PKT;
    __nv_bfloat16* dstl = g_pk_l + (size_t)set*PKT;

    for (int i = tid; i < 64*64; i += 256) {
        int c = i >> 6, p = i & 63;
        s[c][p] = src[((size_t)b*64 + c)*HWs + hw0 + p];
    }
    __syncthreads();

    for (int i = tid; i < 512; i += 256) {
        int p   = i >> 3;
        int cc  = (i >> 1) & 3;
        int sub = i & 1;
        uint32_t ph[4], pl[4];
#pragma unroll
        for (int j = 0; j < 4; j++)
            split2(s[cc*16 + sub*8 + 2*j][p], s[cc*16 + sub*8 + 2*j+1][p], ph[j], pl[j]);
        size_t o = (((size_t)cc*Bsz + b)*HWs + hw0 + p)*16 + sub*8;
        *(uint4*)&dsth[o] = make_uint4(ph[0], ph[1], ph[2], ph[3]);
        *(uint4*)&dstl[o] = make_uint4(pl[0], pl[1], pl[2], pl[3]);
    }
}

// ---------------- post-scatter split -> tensors 2 (d0') / 3 (r0') ----------
__global__ __launch_bounds__(256) void split_feat()
{
    const int tid = threadIdx.x;
    const int hw0 = blockIdx.x * 64;
    const int set = blockIdx.y & 1;
    const int b   = blockIdx.y >> 1;
    const float* src = set ? g_r0 : g_d0;
    __nv_bfloat16* dsth = g_pk_h + (size_t)(2+set)*PKT;
    __nv_bfloat16* dstl = g_pk_l + (size_t)(2+set)*PKT;

    for (int i = tid; i < 512; i += 256) {
        int p   = i >> 3;
        int cc  = (i >> 1) & 3;
        int sub = i & 1;
        const float* sp = src + ((size_t)b*HWs + hw0 + p)*64 + cc*16 + sub*8;
        float4 a = *(const float4*)sp;
        float4 c2 = *(const float4*)(sp + 4);
        float v[8] = {a.x, a.y, a.z, a.w, c2.x, c2.y, c2.z, c2.w};
        uint32_t ph[4], pl[4];
#pragma unroll
        for (int j = 0; j < 4; j++)
            split2(v[2*j], v[2*j+1], ph[j], pl[j]);
        size_t o = (((size_t)cc*Bsz + b)*HWs + hw0 + p)*16 + sub*8;
        *(uint4*)&dsth[o] = make_uint4(ph[0], ph[1], ph[2], ph[3]);
        *(uint4*)&dstl[o] = make_uint4(pl[0], pl[1], pl[2], pl[3]);
    }
}

// ---------------- conv 3x3 SAME via mma, cp.async double-buffered ----------
// grid (Ww/TC, Hh/TR, 2*Bsz): z&1 = set (d/r), z>>1 = b.
// mode 0: stage A (1 source) -> NHWC fp32 g_d0/g_r0.
// mode 1: stage C (2 sources) -> NCHW fp32 to outp (+set offset).
__global__ __launch_bounds__(256) void conv3x3_mma(
    const float* __restrict__ bd0, const float* __restrict__ br0,
    const float* __restrict__ bd2, const float* __restrict__ bd1,
    const float* __restrict__ br2, const float* __restrict__ br1,
    float* __restrict__ outp, int mode)
{
    extern __shared__ __align__(16) unsigned char sraw[];

    const int tid  = threadIdx.x;
    const int lane = tid & 31;
    const int wid  = tid >> 5;
    const int w0c  = blockIdx.x * TC;
    const int h0   = blockIdx.y * TR;
    const int set  = blockIdx.z & 1;
    const int b    = blockIdx.z >> 1;

    float c[8][4];
#pragma unroll
    for (int nf = 0; nf < 8; nf++)
#pragma unroll
        for (int j = 0; j < 4; j++) c[nf][j] = 0.f;

    const int mm   = lane & 15;
    const int kofs = (lane >> 4) << 3;
    const int n_chunks = mode ? 8 : 4;

    auto fill = [&](int icc, unsigned char* sb) {
        int srcsel = icc >> 2, cc = icc & 3;
        int t, wset;
        if (mode == 0)       { t = set;     wset = set; }
        else if (srcsel == 0){ t = 2 + set; wset = 2 + 2*set; }
        else                 { t = set;     wset = 3 + 2*set; }
        const __nv_bfloat16* bh = g_pk_h + (size_t)t*PKT + ((size_t)cc*Bsz + b)*HWs*16;
        const __nv_bfloat16* bl = g_pk_l + (size_t)t*PKT + ((size_t)cc*Bsz + b)*HWs*16;
        uint32_t s_ah = (uint32_t)__cvta_generic_to_shared(sb);
        uint32_t s_al = s_ah + 5760;
        uint32_t s_bf = s_ah + 11520;
        for (int j = tid; j < NCELL*4; j += 256) {
            int cell = j >> 2, q = j & 3;
            int r = cell / HC, cl = cell - r*HC;
            int h = h0 - 1 + r, w = w0c - 1 + cl;
            bool ok = ((unsigned)h < (unsigned)Hh) && ((unsigned)w < (unsigned)Ww);
            const __nv_bfloat16* sp = ((q & 2) ? bl : bh)
                + (ok ? (((size_t)h*Ww + w)*16 + (size_t)((q & 1)*8)) : 0);
            uint32_t dp = ((q & 2) ? s_al : s_ah) + cell*32 + (q & 1)*16;
            CP16(dp, sp, ok ? 16 : 0);
        }
        const uint4* wsrc = (const uint4*)(g_wfrag + (size_t)wset*WSET_U32 + (size_t)cc*9216);
        for (int i = tid; i < 2304; i += 256)
            CP16(s_bf + i*16, wsrc + i, 16);
    };

    fill(0, sraw);
    CPCOMMIT();

#pragma unroll 1
    for (int icc = 0; icc < n_chunks; icc++) {
        unsigned char* cur = sraw + (icc & 1)*BUFB;
        if (icc + 1 < n_chunks) {
            fill(icc + 1, sraw + ((icc + 1) & 1)*BUFB);
            CPCOMMIT();
            CPWAIT(1);
        } else {
            CPWAIT(0);
        }
        __syncthreads();

        uint32_t a_hi = (uint32_t)__cvta_generic_to_shared(cur);
        uint32_t a_lo = a_hi + 5760;
        const uint32_t* s_bf = (const uint32_t*)(cur + 11520);
#pragma unroll
        for (int tap = 0; tap < 9; tap++) {
            const int dy = tap / 3, dx = tap % 3;
            uint32_t aidx = (uint32_t)((((wid + dy)*HC) + (mm + dx))*ICP + kofs) * 2u;
            uint32_t ah[4], al[4];
            ldsm4(ah, a_hi + aidx);
            ldsm4(al, a_lo + aidx);
#pragma unroll
            for (int nf = 0; nf < 8; nf++) {
                uint4 bb = *(const uint4*)&s_bf[((tap*8 + nf)*32 + lane)*4];
                mma_bf16(c[nf], ah, bb.x, bb.y);
                mma_bf16(c[nf], ah, bb.z, bb.w);
                mma_bf16(c[nf], al, bb.x, bb.y);
            }
        }
        __syncthreads();
    }

    if (!mode) {
        // NHWC fp32 epilogue -> g_d0/g_r0
        float* y = set ? g_r0 : g_d0;
        const float* B = set ? br0 : bd0;
        int col0 = lane >> 2;
        size_t rowbase = ((size_t)b*HWs + (size_t)(h0 + wid)*Ww + w0c);
#pragma unroll
        for (int nf = 0; nf < 8; nf++) {
            int oc = nf*8 + (lane & 3)*2;
            float bb0 = B[oc], bb1 = B[oc+1];
            float2 v0, v1;
            v0.x = fmaxf(c[nf][0] + bb0, 0.f);
            v0.y = fmaxf(c[nf][1] + bb1, 0.f);
            v1.x = fmaxf(c[nf][2] + bb0, 0.f);
            v1.y = fmaxf(c[nf][3] + bb1, 0.f);
            *(float2*)&y[(rowbase + col0)*64 + oc]     = v0;
            *(float2*)&y[(rowbase + col0 + 8)*64 + oc] = v1;
        }
    } else {
        // NCHW fp32 epilogue via smem transpose
        float* s_out = (float*)sraw;
        float* y = outp + (size_t)set*Bsz*Cch*HWs;
        {
            int pix0 = wid*16 + (lane >> 2);
            int oc0  = (lane & 3) * 2;
#pragma unroll
            for (int nf = 0; nf < 8; nf++) {
                int oc = nf*8 + oc0;
                s_out[pix0*66 + oc]         = c[nf][0];
                s_out[pix0*66 + oc + 1]     = c[nf][1];
                s_out[(pix0+8)*66 + oc]     = c[nf][2];
                s_out[(pix0+8)*66 + oc + 1] = c[nf][3];
            }
        }
        __syncthreads();
        for (int i = tid; i < 8192; i += 256) {
            int oc = i >> 7;
            int pix = i & 127;
            float bias = set ? (br2[oc] + br1[oc]) : (bd2[oc] + bd1[oc]);
            float v = s_out[pix*66 + oc] + bias;
            v = fmaxf(v, 0.f);
            y[((size_t)(b*Cch + oc))*HWs + (size_t)(h0 + (pix >> 4))*Ww
              + (w0c + (pix & 15))] = v;
        }
    }
}

// ---------------- P1: build feature A-fragments ----------------
__global__ __launch_bounds__(256) void build_feat(
    const int* __restrict__ pc, const int* __restrict__ nbrs,
    const float* __restrict__ disp)
{
    int gw = (blockIdx.x*256 + threadIdx.x) >> 5;
    if (gw >= NTILE) return;
    int lane = threadIdx.x & 31;
    int b = gw / TPB;
    int row0 = (gw - b*TPB) * 16;
    int q = lane & 3;
    int r1 = lane >> 2;
    int rw1 = row0 + r1, rw2 = rw1 + 8;
    int n1 = rw1/9, k1 = rw1 - n1*9;
    int n2 = rw2/9, k2 = rw2 - n2*9;
    int nb1 = nbrs[((size_t)b*NS + n1)*Kn + k1];
    int nb2 = nbrs[((size_t)b*NS + n2)*Kn + k2];
    int p1 = pc[(size_t)b*NS + n1];
    int p2 = pc[(size_t)b*NS + n2];
    const float* d0b = g_d0 + (size_t)b*HWs*64;
    const float* r0b = g_r0 + (size_t)b*HWs*64;
    uint32_t* dst0 = g_ffrag + (((size_t)gw*9)*32 + lane)*8;

#pragma unroll
    for (int dc = 0; dc < 4; dc++) {
        int cA = dc*16 + 2*q, cB = cA + 8;
        float2 nA1 = *(const float2*)&d0b[(size_t)nb1*64 + cA];
        float2 nB1 = *(const float2*)&d0b[(size_t)nb1*64 + cB];
        float2 nA2 = *(const float2*)&d0b[(size_t)nb2*64 + cA];
        float2 nB2 = *(const float2*)&d0b[(size_t)nb2*64 + cB];
        float2 dA1 = *(const float2*)&d0b[(size_t)p1*64 + cA];
        float2 dB1 = *(const float2*)&d0b[(size_t)p1*64 + cB];
        float2 dA2 = *(const float2*)&d0b[(size_t)p2*64 + cA];
        float2 dB2 = *(const float2*)&d0b[(size_t)p2*64 + cB];
        float2 rA1 = *(const float2*)&r0b[(size_t)p1*64 + cA];
        float2 rB1 = *(const float2*)&r0b[(size_t)p1*64 + cB];
        float2 rA2 = *(const float2*)&r0b[(size_t)p2*64 + cA];
        float2 rB2 = *(const float2*)&r0b[(size_t)p2*64 + cB];

        uint32_t h0,h1,h2,h3,l0,l1,l2,l3;
        split2(nA1.x - dA1.x, nA1.y - dA1.y, h0, l0);
        split2(nA2.x - dA2.x, nA2.y - dA2.y, h1, l1);
        split2(nB1.x - dB1.x, nB1.y - dB1.y, h2, l2);
        split2(nB2.x - dB2.x, nB2.y - dB2.y, h3, l3);
        uint32_t* d1 = dst0 + (size_t)dc*32*8;
        *(uint4*)(d1)     = make_uint4(h0, h1, h2, h3);
        *(uint4*)(d1 + 4) = make_uint4(l0, l1, l2, l3);
        split2(nA1.x - rA1.x, nA1.y - rA1.y, h0, l0);
        split2(nA2.x - rA2.x, nA2.y - rA2.y, h1, l1);
        split2(nB1.x - rB1.x, nB1.y - rB1.y, h2, l2);
        split2(nB2.x - rB2.x, nB2.y - rB2.y, h3, l3);
        uint32_t* d2 = dst0 + (size_t)(dc+4)*32*8;
        *(uint4*)(d2)     = make_uint4(h0, h1, h2, h3);
        *(uint4*)(d2 + 4) = make_uint4(l0, l1, l2, l3);
    }
    {
        float v0a = 0.f, v0b = 0.f, v1a = 0.f, v1b = 0.f;
        if (q == 0) {
            v0a = disp[(((size_t)b*3+0)*NS + n1)*Kn + k1];
            v0b = disp[(((size_t)b*3+1)*NS + n1)*Kn + k1];
            v1a = disp[(((size_t)b*3+0)*NS + n2)*Kn + k2];
            v1b = disp[(((size_t)b*3+1)*NS + n2)*Kn + k2];
        } else if (q == 1) {
            v0a = disp[(((size_t)b*3+2)*NS + n1)*Kn + k1];
            v1a = disp[(((size_t)b*3+2)*NS + n2)*Kn + k2];
        }
        uint32_t h0,h1,l0,l1;
        split2(v0a, v0b, h0, l0);
        split2(v1a, v1b, h1, l1);
        uint32_t* d8 = dst0 + (size_t)8*32*8;
        *(uint4*)(d8)     = make_uint4(h0, h1, 0u, 0u);
        *(uint4*)(d8 + 4) = make_uint4(l0, l1, 0u, 0u);
    }
}

// ---------------- P2: fused dual-MLP GEMM -> logits ----------------
__global__ __launch_bounds__(256) void mlp_gemm(
    const float* __restrict__ db1, const float* __restrict__ rb1,
    const float* __restrict__ dw2, const float* __restrict__ rw2)
{
    extern __shared__ uint32_t s_b[];
    const int tid  = threadIdx.x;
    const int lane = tid & 31;
    const int w    = tid >> 5;

    {
        const uint4* src = (const uint4*)g_mfrag;
        uint4* dst = (uint4*)s_b;
        for (int i = tid; i < 5184; i += 256) dst[i] = src[i];
    }
    __syncthreads();

    int t = blockIdx.x*8 + w;
    if (t >= NTILE) return;

    float c[18][4];
#pragma unroll
    for (int nf = 0; nf < 18; nf++)
#pragma unroll
        for (int j = 0; j < 4; j++) c[nf][j] = 0.f;

    const uint4* af = (const uint4*)g_ffrag;
#pragma unroll 1
    for (int chunk = 0; chunk < 9; chunk++) {
        size_t ai = (((size_t)t*9 + chunk)*32 + lane)*2;
        uint4 ahv = af[ai];
        uint4 alv = af[ai + 1];
        uint32_t ah[4] = {ahv.x, ahv.y, ahv.z, ahv.w};
        uint32_t al[4] = {alv.x, alv.y, alv.z, alv.w};
#pragma unroll
        for (int nf = 0; nf < 18; nf++) {
            uint4 bb = *(const uint4*)&s_b[((chunk*18 + nf)*32 + lane)*4];
            mma_bf16(c[nf], ah, bb.x, bb.y);
            mma_bf16(c[nf], ah, bb.z, bb.w);
            mma_bf16(c[nf], al, bb.x, bb.y);
        }
    }

    float sd1 = 0.f, sd2 = 0.f, sr1 = 0.f, sr2 = 0.f;
    int ocq = (lane & 3)*2;
#pragma unroll
    for (int nf = 0; nf < 18; nf++) {
        int jj = (nf < 9) ? (nf*8 + ocq) : ((nf-9)*8 + ocq);
        const float* B1 = (nf < 9) ? db1 : rb1;
        const float* W2 = (nf < 9) ? dw2 : rw2;
        float bb0 = (jj   < Dhh) ? B1[jj]   : 0.f;
        float bb1 = (jj+1 < Dhh) ? B1[jj+1] : 0.f;
        float w20 = (jj   < Dhh) ? W2[jj]   : 0.f;
        float w21 = (jj+1 < Dhh) ? W2[jj+1] : 0.f;
        float h0 = c[nf][0] + bb0; h0 = (h0 > 0.f) ? h0 : 0.2f*h0;
        float h1 = c[nf][1] + bb1; h1 = (h1 > 0.f) ? h1 : 0.2f*h1;
        float h2 = c[nf][2] + bb0; h2 = (h2 > 0.f) ? h2 : 0.2f*h2;
        float h3 = c[nf][3] + bb1; h3 = (h3 > 0.f) ? h3 : 0.2f*h3;
        float s1 = h0*w20 + h1*w21;
        float s2 = h2*w20 + h3*w21;
        if (nf < 9) { sd1 += s1; sd2 += s2; }
        else        { sr1 += s1; sr2 += s2; }
    }
#pragma unroll
    for (int d = 1; d <= 2; d <<= 1) {
        sd1 += __shfl_xor_sync(0xffffffffu, sd1, d);
        sd2 += __shfl_xor_sync(0xffffffffu, sd2, d);
        sr1 += __shfl_xor_sync(0xffffffffu, sr1, d);
        sr2 += __shfl_xor_sync(0xffffffffu, sr2, d);
    }
    if ((lane & 3) == 0) {
        size_t row = (size_t)t*16 + (lane >> 2);
        g_logd[row]     = sd1;
        g_logd[row + 8] = sd2;
        g_logr[row]     = sr1;
        g_logr[row + 8] = sr2;
    }
}

// ---------------- P3: softmax + weighted neighbor sum ----------------
__global__ __launch_bounds__(64) void point_softmax(
    const int* __restrict__ nbrs,
    const float* __restrict__ d_bias, const float* __restrict__ r_bias)
{
    const int n = blockIdx.x;
    const int b = blockIdx.y;
    const int tid = threadIdx.x;
    __shared__ int s_nb[9];
    if (tid < Kn) s_nb[tid] = nbrs[((size_t)b*NS + n)*Kn + tid];
    __syncthreads();

    size_t base = ((size_t)b*NS + n)*Kn;
    float ld[9], lr[9];
    float mxd = -1e30f, mxr = -1e30f;
#pragma unroll
    for (int k = 0; k < Kn; k++) {
        ld[k] = g_logd[base + k];
        lr[k] = g_logr[base + k];
        mxd = fmaxf(mxd, ld[k]);
        mxr = fmaxf(mxr, lr[k]);
    }
    float sd = 0.f, sr = 0.f;
#pragma unroll
    for (int k = 0; k < Kn; k++) {
        ld[k] = expf(ld[k] - mxd); sd += ld[k];
        lr[k] = expf(lr[k] - mxr); sr += lr[k];
    }
    float invd = 1.f/sd, invr = 1.f/sr;
#pragma unroll
    for (int k = 0; k < Kn; k++) { ld[k] *= invd; lr[k] *= invr; }

    const float* d0b = g_d0 + (size_t)b*HWs*64;
    int ch = tid;
    float ad = d_bias[ch], ar = r_bias[ch];
#pragma unroll
    for (int k = 0; k < Kn; k++) {
        float dn = d0b[(size_t)s_nb[k]*64 + ch];
        ad = fmaf(ld[k], dn, ad);
        ar = fmaf(lr[k], dn, ar);
    }
    g_dfeat[((size_t)b*Cch + ch)*NS + n] = ad;
    g_rfeat[((size_t)b*Cch + ch)*NS + n] = ar;
}

// ---------------- scatter (NHWC, unique pc indices) ----------------
__global__ __launch_bounds__(128) void scatter_kernel(const int* __restrict__ pc)
{
    const int n = blockIdx.x;
    const int b = blockIdx.y;
    const int tid = threadIdx.x;
    const int idx = pc[(size_t)b*NS + n];

    if (tid < 64) {
        int ch = tid;
        float v = g_dfeat[((size_t)b*Cch + ch)*NS + n];
        size_t o = ((size_t)b*HWs + idx)*64 + ch;
        g_d0[o] = (ch == 0) ? v : (g_d0[o] + v);
    } else {
        int ch = tid - 64;
        float v = g_rfeat[((size_t)b*Cch + ch)*NS + n];
        size_t o = ((size_t)b*HWs + idx)*64 + ch;
        g_r0[o] = (ch == 0) ? v : (g_r0[o] + v);
    }
}

// ---------------------------------------------------------------------------
extern "C" void kernel_launch(void* const* d_in, const int* in_sizes, int n_in,
                              void* d_out, int out_size)
{
    const float* rgb    = (const float*)d_in[0];
    const float* sdepth = (const float*)d_in[1];
    const int*   pc     = (const int*)  d_in[2];
    const int*   nbrs   = (const int*)  d_in[3];
    const float* disp   = (const float*)d_in[4];
    const float* d_c0w  = (const float*)d_in[5];
    const float* d_c0b  = (const float*)d_in[6];
    const float* d_c1w  = (const float*)d_in[7];
    const float* d_c1b  = (const float*)d_in[8];
    const float* d_c2w  = (const float*)d_in[9];
    const float* d_c2b  = (const float*)d_in[10];
    const float* r_c0w  = (const float*)d_in[11];
    const float* r_c0b  = (const float*)d_in[12];
    const float* r_c1w  = (const float*)d_in[13];
    const float* r_c1b  = (const float*)d_in[14];
    const float* r_c2w  = (const float*)d_in[15];
    const float* r_c2b  = (const float*)d_in[16];
    const float* d_w1   = (const float*)d_in[17];
    const float* d_b1   = (const float*)d_in[18];
    const float* d_w2   = (const float*)d_in[19];
    const float* d_b2   = (const float*)d_in[20];
    const float* r_w1   = (const float*)d_in[21];
    const float* r_b1   = (const float*)d_in[22];
    const float* r_w2   = (const float*)d_in[23];
    const float* r_b2   = (const float*)d_in[24];
    const float* d_bias = (const float*)d_in[25];
    const float* r_bias = (const float*)d_in[26];
    float* out = (float*)d_out;
    (void)d_b2; (void)r_b2;   // softmax is shift-invariant

    cudaFuncSetAttribute(conv3x3_mma,
                         cudaFuncAttributeMaxDynamicSharedMemorySize, SMEM_CONV);
    cudaFuncSetAttribute(mlp_gemm,
                         cudaFuncAttributeMaxDynamicSharedMemorySize, 82944);

    // weight prepacks: conv sets 0:d0 1:r0 2:d2 3:d1 4:r2 5:r1
    prepack_w<<<dim3(288, 6), 32>>>(d_c0w, r_c0w, d_c2w, d_c1w, r_c2w, r_c1w);
    prepack_mlp<<<162, 32>>>(d_w1, r_w1);
    prepack_src<<<dim3(HWs/64, 2*Bsz), 256>>>(sdepth, rgb);

    dim3 cgrid(Ww/TC, Hh/TR, 2*Bsz);

    // Stage A (both tensors, both batches in one launch) -> NHWC fp32
    conv3x3_mma<<<cgrid, 256, SMEM_CONV>>>(d_c0b, r_c0b,
                                           nullptr, nullptr, nullptr, nullptr,
                                           nullptr, 0);

    // Stage B: tensorized point MLP
    build_feat<<<(NTILE*32 + 255)/256, 256>>>(pc, nbrs, disp);
    mlp_gemm<<<(NTILE + 7)/8, 256, 82944>>>(d_b1, r_b1, d_w2, r_w2);
    point_softmax<<<dim3(NS, Bsz), 64>>>(nbrs, d_bias, r_bias);
    scatter_kernel<<<dim3(NS, Bsz), 128>>>(pc);

    // split updated features for stage C
    split_feat<<<dim3(HWs/64, 2*Bsz), 256>>>();

    // Stage C (fused dual-source, both tensors in one launch) -> NCHW out
    conv3x3_mma<<<cgrid, 256, SMEM_CONV>>>(nullptr, nullptr,
                                           d_c2b, d_c1b, r_c2b, r_c1b,
                                           out, 1);
}